// round 6
// baseline (speedup 1.0000x reference)
#include <cuda_runtime.h>
#include <cstdint>
#include <math.h>

#define HIDDEN      2048
#define GATE_IN     2608
#define GATE_IN_PAD 2624        // 82 * 32
#define STAT_W      576         // 2624 - 2048 (560 data + 16 zero)
#define GATE_HID    1024
#define NH          16
#define HD          128
#define NP          5
#define OUT_DIM     80
#define MAX_NT      8192

// GEMM1: CTA 128x256, 16 warps (2M x 8N, warp 64x32), 3-stage cp.async
#define KCHUNK      32
#define NCHUNK      (GATE_IN_PAD / KCHUNK)   // 82
#define HID_CHUNKS  (HIDDEN / KCHUNK)        // 64
#define SM_STRIDE   36
#define G1_A_FLOATS (128 * SM_STRIDE)
#define G1_B_FLOATS (256 * SM_STRIDE)
#define G1_STAGE_F  (G1_A_FLOATS + G1_B_FLOATS)       // 13824 floats
#define GEMM1_SMEM  (3 * G1_STAGE_F * 4)              // 165888 B

// GEMM2: CTA 64(M) x 80(N), 8 warps (4M x 2N, warp 16x40), K=1024
#define G2_KC       32
#define G2_NCH      (GATE_HID / G2_KC)
#define G2_A_FLOATS (64 * SM_STRIDE)
#define G2_B_FLOATS (80 * SM_STRIDE)
#define GEMM2_SMEM  ((2 * (G2_A_FLOATS + G2_B_FLOATS)) * 4)

// Static scratch
__device__ float g_stats[(size_t)MAX_NT * STAT_W];
__device__ float g_w1p[(size_t)GATE_HID * GATE_IN_PAD];
__device__ float g_w2p[(size_t)OUT_DIM * GATE_HID];
__device__ float g_h[(size_t)MAX_NT * GATE_HID];
__device__ float g_probs[(size_t)MAX_NT * OUT_DIM];

// ---------------------------------------------------------------------------
// helpers
// ---------------------------------------------------------------------------
__device__ __forceinline__ float wredsum(float v) {
#pragma unroll
    for (int o = 16; o; o >>= 1) v += __shfl_xor_sync(0xffffffffu, v, o);
    return v;
}
__device__ __forceinline__ float tf32r(float x) {
    float y;
    asm("cvt.rna.tf32.f32 %0, %1;" : "=f"(y) : "f"(x));
    return y;
}
__device__ __forceinline__ void cp_async16(uint32_t dst, const void* src) {
    asm volatile("cp.async.cg.shared.global [%0], [%1], 16;" :: "r"(dst), "l"(src));
}
__device__ __forceinline__ uint32_t smem_u32(const void* p) {
    uint32_t a;
    asm("{ .reg .u64 t; cvta.to.shared.u64 t, %1; cvt.u32.u64 %0, t; }" : "=r"(a) : "l"(p));
    return a;
}
__device__ __forceinline__ float gelu(float x) {
    return 0.5f * x * (1.0f + erff(x * 0.70710678118654752f));
}
// PTX m16n8k8 tf32: a0=A[g][t] a1=A[g+8][t] a2=A[g][t+4] a3=A[g+8][t+4]
//                   b0=B[k=t][n=g] b1=B[k=t+4][n=g]
//                   c0=(g,2t) c1=(g,2t+1) c2=(g+8,2t) c3=(g+8,2t+1)
__device__ __forceinline__ void mma_tf32_16x8x8(float c[4],
                                                uint32_t a0, uint32_t a1,
                                                uint32_t a2, uint32_t a3,
                                                uint32_t b0, uint32_t b1) {
    asm("mma.sync.aligned.m16n8k8.row.col.f32.tf32.tf32.f32 "
        "{%0,%1,%2,%3}, {%4,%5,%6,%7}, {%8,%9}, {%0,%1,%2,%3};"
        : "+f"(c[0]), "+f"(c[1]), "+f"(c[2]), "+f"(c[3])
        : "r"(a0), "r"(a1), "r"(a2), "r"(a3), "r"(b0), "r"(b1));
}

// ---------------------------------------------------------------------------
// Kernel A: per-token path stats -> g_stats[t][576] (tf32-rounded).
// Layout (offset within row): stats[h][p][4] at 0, norms[h][p] at 320,
// pairwise[h][10] at 400, zeros 560..575.
// ---------------------------------------------------------------------------
__global__ void __launch_bounds__(512) stats_kernel(
    const float* __restrict__ p0, const float* __restrict__ p1,
    const float* __restrict__ p2, const float* __restrict__ p3,
    const float* __restrict__ p4)
{
    const int t   = blockIdx.x;
    const int tid = threadIdx.x;
    float* gate = g_stats + (size_t)t * STAT_W;

    if (tid < 4) {
        float4 z = {0.f, 0.f, 0.f, 0.f};
        reinterpret_cast<float4*>(gate + 560)[tid] = z;
    }

    const int w = tid >> 5, lane = tid & 31;
    const float* pp[NP] = {p0, p1, p2, p3, p4};
    const size_t base = (size_t)t * (NH * HD) + (size_t)w * HD + lane * 4;

    float4 v[NP];
#pragma unroll
    for (int p = 0; p < NP; p++) v[p] = *reinterpret_cast<const float4*>(pp[p] + base);

    float vals[25];
#pragma unroll
    for (int p = 0; p < NP; p++) {
        vals[p]      = v[p].x + v[p].y + v[p].z + v[p].w;
        vals[5 + p]  = v[p].x * v[p].x + v[p].y * v[p].y + v[p].z * v[p].z + v[p].w * v[p].w;
        vals[10 + p] = fabsf(v[p].x) + fabsf(v[p].y) + fabsf(v[p].z) + fabsf(v[p].w);
    }
    {
        int k = 15;
#pragma unroll
        for (int p = 0; p < NP; p++)
#pragma unroll
            for (int q = p + 1; q < NP; q++)
                vals[k++] = v[p].x * v[q].x + v[p].y * v[q].y + v[p].z * v[q].z + v[p].w * v[q].w;
    }
#pragma unroll
    for (int i = 0; i < 25; i++) vals[i] = wredsum(vals[i]);

    if (lane == 0) {
        const float inv = 1.0f / 128.0f;
        float sq[NP];
#pragma unroll
        for (int p = 0; p < NP; p++) {
            float mean = vals[p] * inv;
            sq[p] = vals[5 + p];
            float l2 = sqrtf(sq[p]);
            float var = sq[p] * inv - mean * mean;
            float am  = vals[10 + p] * inv;
            float* s = gate + w * (NP * 4) + p * 4;
            s[0] = tf32r(mean); s[1] = tf32r(var); s[2] = tf32r(am); s[3] = tf32r(l2);
            gate[320 + w * NP + p] = tf32r(l2);
        }
        int kk = 0;
#pragma unroll
        for (int p = 0; p < NP; p++)
#pragma unroll
            for (int q = p + 1; q < NP; q++) {
                float d2 = sq[p] + sq[q] - 2.0f * vals[15 + kk];
                gate[400 + w * 10 + kk] = tf32r(sqrtf(fmaxf(d2, 0.0f)));
                kk++;
            }
    }
}

// ---------------------------------------------------------------------------
// Weight repacks (tf32-rounded; W1 zero-padded in K).
// ---------------------------------------------------------------------------
__global__ void pack_w1_kernel(const float* __restrict__ W1)
{
    const int idx = blockIdx.x * 256 + threadIdx.x;
    const int total = GATE_HID * (GATE_IN_PAD / 4);
    if (idx >= total) return;
    const int row = idx / (GATE_IN_PAD / 4);
    const int c4  = idx % (GATE_IN_PAD / 4);
    float4 v = {0.f, 0.f, 0.f, 0.f};
    if (c4 < GATE_IN / 4)
        v = reinterpret_cast<const float4*>(W1 + (size_t)row * GATE_IN)[c4];
    v.x = tf32r(v.x); v.y = tf32r(v.y); v.z = tf32r(v.z); v.w = tf32r(v.w);
    reinterpret_cast<float4*>(g_w1p + (size_t)row * GATE_IN_PAD)[c4] = v;
}

__global__ void pack_w2_kernel(const float* __restrict__ W2)
{
    const int idx = blockIdx.x * 256 + threadIdx.x;
    const int total = OUT_DIM * (GATE_HID / 4);
    if (idx >= total) return;
    float4 v = reinterpret_cast<const float4*>(W2)[idx];
    v.x = tf32r(v.x); v.y = tf32r(v.y); v.z = tf32r(v.z); v.w = tf32r(v.w);
    reinterpret_cast<float4*>(g_w2p)[idx] = v;
}

// ---------------------------------------------------------------------------
// Kernel B: GEMM1 via mma.sync tf32.  h = tf32(GELU(gate @ W1p^T + b1))
// A assembled on the fly: k<2048 from hidden (tf32r applied here), k>=2048
// from g_stats. CTA 128x256, 16 warps (warp 64x32), 3-stage cp.async.
// ---------------------------------------------------------------------------
__device__ __forceinline__ void g1_load(uint32_t stage_s,
                                        const float* __restrict__ hid,
                                        const float* __restrict__ st,
                                        const float* __restrict__ Bm,
                                        int k0, int tid)
{
    const uint32_t a_s = stage_s;
    const uint32_t b_s = stage_s + G1_A_FLOATS * 4;
    if (k0 < HIDDEN) {
#pragma unroll
        for (int j = 0; j < 2; j++) {                 // A: 1024 f4 / 512 thr
            const int idx = tid + j * 512;
            const int m  = idx >> 3;
            const int ks = (idx & 7) << 2;
            cp_async16(a_s + (uint32_t)(m * SM_STRIDE + ks) * 4,
                       hid + (size_t)m * HIDDEN + k0 + ks);
        }
    } else {
#pragma unroll
        for (int j = 0; j < 2; j++) {
            const int idx = tid + j * 512;
            const int m  = idx >> 3;
            const int ks = (idx & 7) << 2;
            cp_async16(a_s + (uint32_t)(m * SM_STRIDE + ks) * 4,
                       st + (size_t)m * STAT_W + (k0 - HIDDEN) + ks);
        }
    }
#pragma unroll
    for (int j = 0; j < 4; j++) {                     // B: 2048 f4 / 512 thr
        const int idx = tid + j * 512;
        const int m  = idx >> 3;
        const int ks = (idx & 7) << 2;
        cp_async16(b_s + (uint32_t)(m * SM_STRIDE + ks) * 4,
                   Bm + (size_t)m * GATE_IN_PAD + k0 + ks);
    }
}

__global__ void __launch_bounds__(512, 1) gemm1_mma_kernel(const float* __restrict__ hidden,
                                                           const float* __restrict__ b1)
{
    extern __shared__ float smem[];
    const uint32_t s0 = smem_u32(smem);

    const int tid  = threadIdx.x;
    const int wid  = tid >> 5, lane = tid & 31;
    const int wm   = (wid & 1) * 64;        // warp M origin (2 M-warps)
    const int wn   = (wid >> 1) * 32;       // warp N origin (8 N-warps)
    const int g    = lane >> 2;
    const int t    = lane & 3;

    const float* hid = hidden  + (size_t)blockIdx.y * 128 * HIDDEN;
    const float* st  = g_stats + (size_t)blockIdx.y * 128 * STAT_W;
    const float* Bm  = g_w1p   + (size_t)blockIdx.x * 256 * GATE_IN_PAD;

    float acc[4][4][4];
#pragma unroll
    for (int i = 0; i < 4; i++)
#pragma unroll
        for (int j = 0; j < 4; j++)
#pragma unroll
            for (int r = 0; r < 4; r++) acc[i][j][r] = 0.0f;

    // prologue: chunks 0,1 into stages 0,1
    g1_load(s0, hid, st, Bm, 0, tid);
    asm volatile("cp.async.commit_group;" ::: "memory");
    g1_load(s0 + (uint32_t)G1_STAGE_F * 4, hid, st, Bm, KCHUNK, tid);
    asm volatile("cp.async.commit_group;" ::: "memory");

    int stage_rd = 0;
    for (int i = 0; i < NCHUNK; i++) {
        if (i + 2 < NCHUNK) {
            const int ws = (i + 2) % 3;
            g1_load(s0 + (uint32_t)(ws * G1_STAGE_F) * 4, hid, st, Bm,
                    (i + 2) * KCHUNK, tid);
        }
        asm volatile("cp.async.commit_group;" ::: "memory");
        asm volatile("cp.async.wait_group 2;" ::: "memory");
        __syncthreads();

        const float* as = smem + stage_rd * G1_STAGE_F;
        const float* bs = as + G1_A_FLOATS;

#pragma unroll
        for (int kk = 0; kk < KCHUNK; kk += 8) {
            uint32_t a[4][4];
#pragma unroll
            for (int mi = 0; mi < 4; mi++) {
                const float* r0 = as + (wm + mi * 16 + g) * SM_STRIDE + kk;
                const float* r1 = as + (wm + mi * 16 + g + 8) * SM_STRIDE + kk;
                a[mi][0] = __float_as_uint(r0[t]);
                a[mi][1] = __float_as_uint(r1[t]);
                a[mi][2] = __float_as_uint(r0[t + 4]);
                a[mi][3] = __float_as_uint(r1[t + 4]);
            }
            uint32_t b[4][2];
#pragma unroll
            for (int nj = 0; nj < 4; nj++) {
                const float* br = bs + (wn + nj * 8 + g) * SM_STRIDE + kk;
                b[nj][0] = __float_as_uint(br[t]);
                b[nj][1] = __float_as_uint(br[t + 4]);
            }
#pragma unroll
            for (int mi = 0; mi < 4; mi++)
#pragma unroll
                for (int nj = 0; nj < 4; nj++)
                    mma_tf32_16x8x8(acc[mi][nj], a[mi][0], a[mi][1], a[mi][2], a[mi][3],
                                    b[nj][0], b[nj][1]);
        }
        __syncthreads();
        stage_rd = (stage_rd + 1) % 3;
    }

    // NOTE: hidden values enter the MMA un-rounded (raw fp32 -> tf32 truncation
    // by HW uses RZ on mantissa bits beyond 10); W1 is rna-rounded. Error still
    // ~2^-11 per element, comfortably inside budget (R5 measured 3.2e-4 with
    // both rna — expect <= ~4e-4 here).

    // epilogue: bias + exact GELU, tf32-rounded -> g_h
    const size_t row_base = (size_t)blockIdx.y * 128 + wm + g;
    const int    col_base = blockIdx.x * 256 + wn + 2 * t;
#pragma unroll
    for (int nj = 0; nj < 4; nj++) {
        const int gc = col_base + nj * 8;
        const float2 bb = *reinterpret_cast<const float2*>(b1 + gc);
#pragma unroll
        for (int mi = 0; mi < 4; mi++) {
            const size_t r0 = row_base + mi * 16;
            float2 o0, o1;
            o0.x = tf32r(gelu(acc[mi][nj][0] + bb.x));
            o0.y = tf32r(gelu(acc[mi][nj][1] + bb.y));
            o1.x = tf32r(gelu(acc[mi][nj][2] + bb.x));
            o1.y = tf32r(gelu(acc[mi][nj][3] + bb.y));
            *reinterpret_cast<float2*>(g_h + r0 * GATE_HID + gc)       = o0;
            *reinterpret_cast<float2*>(g_h + (r0 + 8) * GATE_HID + gc) = o1;
        }
    }
}

// ---------------------------------------------------------------------------
// Kernel C: GEMM2 via mma.sync tf32 + fused bias/softmax/clip/renorm.
// ---------------------------------------------------------------------------
__global__ void __launch_bounds__(256) gemm2_mma_kernel(
    const float* __restrict__ b2, const float* __restrict__ log_temp)
{
    extern __shared__ float smem[];
    const uint32_t s0 = smem_u32(smem);

    const int tid  = threadIdx.x;
    const int wid  = tid >> 5, lane = tid & 31;
    const int mw   = wid >> 1;
    const int nw   = wid & 1;
    const int g    = lane >> 2;
    const int t    = lane & 3;

    const int tbase = blockIdx.x * 64;
    const float* A = g_h + (size_t)tbase * GATE_HID;

    float acc[5][4];
#pragma unroll
    for (int j = 0; j < 5; j++)
#pragma unroll
        for (int r = 0; r < 4; r++) acc[j][r] = 0.0f;

    const uint32_t aoff[2] = {0u, (uint32_t)G2_A_FLOATS * 4};
    const uint32_t boff[2] = {(uint32_t)(2 * G2_A_FLOATS) * 4,
                              (uint32_t)(2 * G2_A_FLOATS + G2_B_FLOATS) * 4};

    {
#pragma unroll
        for (int j = 0; j < 2; j++) {
            const int idx = tid + j * 256;
            const int m = idx >> 3, ks = (idx & 7) << 2;
            cp_async16(s0 + aoff[0] + (uint32_t)(m * SM_STRIDE + ks) * 4,
                       A + (size_t)m * GATE_HID + ks);
        }
#pragma unroll
        for (int j = 0; j < 3; j++) {
            const int idx = tid + j * 256;
            if (idx < 640) {
                const int m = idx >> 3, ks = (idx & 7) << 2;
                cp_async16(s0 + boff[0] + (uint32_t)(m * SM_STRIDE + ks) * 4,
                           g_w2p + (size_t)m * GATE_HID + ks);
            }
        }
        asm volatile("cp.async.commit_group;" ::: "memory");
    }

    for (int i = 0; i < G2_NCH; i++) {
        const int s = i & 1;
        if (i + 1 < G2_NCH) {
            const int ns = (i + 1) & 1;
            const int k0 = (i + 1) * G2_KC;
#pragma unroll
            for (int j = 0; j < 2; j++) {
                const int idx = tid + j * 256;
                const int m = idx >> 3, ks = (idx & 7) << 2;
                cp_async16(s0 + aoff[ns] + (uint32_t)(m * SM_STRIDE + ks) * 4,
                           A + (size_t)m * GATE_HID + k0 + ks);
            }
#pragma unroll
            for (int j = 0; j < 3; j++) {
                const int idx = tid + j * 256;
                if (idx < 640) {
                    const int m = idx >> 3, ks = (idx & 7) << 2;
                    cp_async16(s0 + boff[ns] + (uint32_t)(m * SM_STRIDE + ks) * 4,
                               g_w2p + (size_t)m * GATE_HID + k0 + ks);
                }
            }
        }
        asm volatile("cp.async.commit_group;" ::: "memory");
        if (i + 1 < G2_NCH) asm volatile("cp.async.wait_group 1;" ::: "memory");
        else                asm volatile("cp.async.wait_group 0;" ::: "memory");
        __syncthreads();

        const float* as = smem + (s ? G2_A_FLOATS : 0);
        const float* bs = smem + 2 * G2_A_FLOATS + (s ? G2_B_FLOATS : 0);

#pragma unroll
        for (int kk = 0; kk < G2_KC; kk += 8) {
            const float* r0 = as + (mw * 16 + g) * SM_STRIDE + kk;
            const float* r1 = as + (mw * 16 + g + 8) * SM_STRIDE + kk;
            uint32_t a0 = __float_as_uint(r0[t]);
            uint32_t a1 = __float_as_uint(r1[t]);
            uint32_t a2 = __float_as_uint(r0[t + 4]);
            uint32_t a3 = __float_as_uint(r1[t + 4]);
#pragma unroll
            for (int nj = 0; nj < 5; nj++) {
                const float* br = bs + (nw * 40 + nj * 8 + g) * SM_STRIDE + kk;
                mma_tf32_16x8x8(acc[nj], a0, a1, a2, a3,
                                __float_as_uint(br[t]), __float_as_uint(br[t + 4]));
            }
        }
        __syncthreads();
    }

    float* lg = smem;
    {
        const int r0 = mw * 16 + g;
        const int c0 = nw * 40 + 2 * t;
#pragma unroll
        for (int nj = 0; nj < 5; nj++) {
            const int c = c0 + nj * 8;
            lg[r0 * OUT_DIM + c]            = acc[nj][0];
            lg[r0 * OUT_DIM + c + 1]        = acc[nj][1];
            lg[(r0 + 8) * OUT_DIM + c]      = acc[nj][2];
            lg[(r0 + 8) * OUT_DIM + c + 1]  = acc[nj][3];
        }
    }
    __syncthreads();

#pragma unroll
    for (int it = 0; it < 4; it++) {
        const int idx = tid + it * 256;
        const int tt = idx >> 4, h = idx & 15;
        const float invt = expf(-log_temp[h]);
        float l[NP], mx = -1e30f;
#pragma unroll
        for (int p = 0; p < NP; p++) {
            l[p] = (lg[tt * OUT_DIM + h * NP + p] + __ldg(b2 + h * NP + p)) * invt;
            mx = fmaxf(mx, l[p]);
        }
        float e[NP], se = 0.f;
#pragma unroll
        for (int p = 0; p < NP; p++) { e[p] = expf(l[p] - mx); se += e[p]; }
        const float ise = 1.0f / se;
        float pr[NP], s2s = 0.f;
#pragma unroll
        for (int p = 0; p < NP; p++) { pr[p] = fmaxf(e[p] * ise, 0.02f); s2s += pr[p]; }
        const float is2 = 1.0f / s2s;
        float* dst = g_probs + (size_t)(tbase + tt) * OUT_DIM + h * NP;
#pragma unroll
        for (int p = 0; p < NP; p++) dst[p] = pr[p] * is2;
    }
}

// ---------------------------------------------------------------------------
// Kernel D: weighted path combine.
// ---------------------------------------------------------------------------
__global__ void output_kernel(
    const float* __restrict__ p0, const float* __restrict__ p1,
    const float* __restrict__ p2, const float* __restrict__ p3,
    const float* __restrict__ p4, float* __restrict__ out, int n4)
{
    const int v = blockIdx.x * blockDim.x + threadIdx.x;
    if (v >= n4) return;
    const int t = v >> 9;
    const int h = (v >> 5) & 15;
    const float* pb = g_probs + (size_t)t * OUT_DIM + h * NP;
    const float w0 = pb[0], w1 = pb[1], w2 = pb[2], w3 = pb[3], w4 = pb[4];
    const float4 a0 = reinterpret_cast<const float4*>(p0)[v];
    const float4 a1 = reinterpret_cast<const float4*>(p1)[v];
    const float4 a2 = reinterpret_cast<const float4*>(p2)[v];
    const float4 a3 = reinterpret_cast<const float4*>(p3)[v];
    const float4 a4 = reinterpret_cast<const float4*>(p4)[v];
    float4 o;
    o.x = a0.x * w0 + a1.x * w1 + a2.x * w2 + a3.x * w3 + a4.x * w4;
    o.y = a0.y * w0 + a1.y * w1 + a2.y * w2 + a3.y * w3 + a4.y * w4;
    o.z = a0.z * w0 + a1.z * w1 + a2.z * w2 + a3.z * w3 + a4.z * w4;
    o.w = a0.w * w0 + a1.w * w1 + a2.w * w2 + a3.w * w3 + a4.w * w4;
    reinterpret_cast<float4*>(out)[v] = o;
}

__global__ void zero_tail_kernel(float* out, int start, int total)
{
    const int i = start + blockIdx.x * blockDim.x + threadIdx.x;
    if (i < total) out[i] = 0.0f;
}

// ---------------------------------------------------------------------------
extern "C" void kernel_launch(void* const* d_in, const int* in_sizes, int n_in,
                              void* d_out, int out_size)
{
    const float* hidden = (const float*)d_in[0];
    const float* p0 = (const float*)d_in[1];
    const float* p1 = (const float*)d_in[2];
    const float* p2 = (const float*)d_in[3];
    const float* p3 = (const float*)d_in[4];
    const float* p4 = (const float*)d_in[5];
    const float* W1 = (const float*)d_in[6];
    const float* b1 = (const float*)d_in[7];
    const float* W2 = (const float*)d_in[8];
    const float* b2 = (const float*)d_in[9];
    const float* lt = (const float*)d_in[10];

    const int NT = in_sizes[0] / HIDDEN;   // 8192

    static int smem_set = 0;
    if (!smem_set) {
        cudaFuncSetAttribute(gemm1_mma_kernel,
                             cudaFuncAttributeMaxDynamicSharedMemorySize, GEMM1_SMEM);
        cudaFuncSetAttribute(gemm2_mma_kernel,
                             cudaFuncAttributeMaxDynamicSharedMemorySize, GEMM2_SMEM);
        smem_set = 1;
    }

    {
        const int t1 = GATE_HID * (GATE_IN_PAD / 4);
        pack_w1_kernel<<<(t1 + 255) / 256, 256>>>(W1);
        const int t2 = OUT_DIM * (GATE_HID / 4);
        pack_w2_kernel<<<(t2 + 255) / 256, 256>>>(W2);
    }
    stats_kernel<<<NT, 512>>>(p0, p1, p2, p3, p4);

    dim3 g1(GATE_HID / 256, NT / 128);   // (4, 64)
    gemm1_mma_kernel<<<g1, 512, GEMM1_SMEM>>>(hidden, b1);

    gemm2_mma_kernel<<<NT / 64, 256, GEMM2_SMEM>>>(b2, lt);

    const int n4 = NT * (NH * HD) / 4;
    output_kernel<<<(n4 + 255) / 256, 256>>>(p0, p1, p2, p3, p4, (float*)d_out, n4);

    const int nout = NT * NH * HD;
    if (out_size > nout) {
        const int extra = out_size - nout;
        zero_tail_kernel<<<(extra + 255) / 256, 256>>>((float*)d_out, nout, out_size);
    }
}

// round 7
// speedup vs baseline: 1.0409x; 1.0409x over previous
#include <cuda_runtime.h>
#include <cstdint>
#include <math.h>

#define HIDDEN      2048
#define GATE_IN     2608
#define GATE_IN_PAD 2624        // 82 * 32
#define STAT_W      576         // 560 data + 16 zero pad
#define GATE_HID    1024
#define NH          16
#define HD          128
#define NP          5
#define OUT_DIM     80
#define MAX_NT      8192

// GEMM1: CTA 128x256, 8 warps (2M x 4N, warp 64x64), 3-stage cp.async
#define KCHUNK      32
#define NCHUNK      (GATE_IN_PAD / KCHUNK)   // 82
#define SM_STRIDE   36
#define G1_A_FLOATS (128 * SM_STRIDE)         // 4608
#define G1_B_FLOATS (256 * SM_STRIDE)         // 9216
#define G1_STAGE_F  (G1_A_FLOATS + G1_B_FLOATS)
#define GEMM1_SMEM  (3 * G1_STAGE_F * 4)      // 165888

// GEMM2: CTA 64(M) x 80(N), 8 warps (4M x 2N, warp 16x40), K=1024
#define G2_KC       32
#define G2_NCH      (GATE_HID / G2_KC)
#define G2_A_FLOATS (64 * SM_STRIDE)
#define G2_B_FLOATS (80 * SM_STRIDE)
#define GEMM2_SMEM  ((2 * (G2_A_FLOATS + G2_B_FLOATS)) * 4)

// Static scratch
__device__ float g_stats[(size_t)MAX_NT * STAT_W];
__device__ float g_w1p[(size_t)GATE_HID * GATE_IN_PAD];
__device__ float g_w2p[(size_t)OUT_DIM * GATE_HID];
__device__ float g_h[(size_t)MAX_NT * GATE_HID];
__device__ float g_probs[(size_t)MAX_NT * OUT_DIM];

// ---------------------------------------------------------------------------
// helpers
// ---------------------------------------------------------------------------
__device__ __forceinline__ float wredsum(float v) {
#pragma unroll
    for (int o = 16; o; o >>= 1) v += __shfl_xor_sync(0xffffffffu, v, o);
    return v;
}
__device__ __forceinline__ float tf32r(float x) {
    float y;
    asm("cvt.rna.tf32.f32 %0, %1;" : "=f"(y) : "f"(x));
    return y;
}
__device__ __forceinline__ void cp_async16(uint32_t dst, const void* src) {
    asm volatile("cp.async.cg.shared.global [%0], [%1], 16;" :: "r"(dst), "l"(src));
}
__device__ __forceinline__ uint32_t smem_u32(const void* p) {
    uint32_t a;
    asm("{ .reg .u64 t; cvta.to.shared.u64 t, %1; cvt.u32.u64 %0, t; }" : "=r"(a) : "l"(p));
    return a;
}
__device__ __forceinline__ float gelu(float x) {
    return 0.5f * x * (1.0f + erff(x * 0.70710678118654752f));
}
// PTX m16n8k8 tf32: a0=A[g][t] a1=A[g+8][t] a2=A[g][t+4] a3=A[g+8][t+4]
//                   b0=B[k=t][n=g] b1=B[k=t+4][n=g]
//                   c0=(g,2t) c1=(g,2t+1) c2=(g+8,2t) c3=(g+8,2t+1)
__device__ __forceinline__ void mma_tf32_16x8x8(float c[4],
                                                uint32_t a0, uint32_t a1,
                                                uint32_t a2, uint32_t a3,
                                                uint32_t b0, uint32_t b1) {
    asm("mma.sync.aligned.m16n8k8.row.col.f32.tf32.tf32.f32 "
        "{%0,%1,%2,%3}, {%4,%5,%6,%7}, {%8,%9}, {%0,%1,%2,%3};"
        : "+f"(c[0]), "+f"(c[1]), "+f"(c[2]), "+f"(c[3])
        : "r"(a0), "r"(a1), "r"(a2), "r"(a3), "r"(b0), "r"(b1));
}

// ---------------------------------------------------------------------------
// Kernel A: per-token path stats -> g_stats[t][576] (tf32-rounded).
// stats[h][p][4] at 0, norms[h][p] at 320, pairwise[h][10] at 400, zeros 560+.
// ---------------------------------------------------------------------------
__global__ void __launch_bounds__(512) stats_kernel(
    const float* __restrict__ p0, const float* __restrict__ p1,
    const float* __restrict__ p2, const float* __restrict__ p3,
    const float* __restrict__ p4)
{
    const int t   = blockIdx.x;
    const int tid = threadIdx.x;
    float* gate = g_stats + (size_t)t * STAT_W;

    if (tid < 4) {
        float4 z = {0.f, 0.f, 0.f, 0.f};
        reinterpret_cast<float4*>(gate + 560)[tid] = z;
    }

    const int w = tid >> 5, lane = tid & 31;
    const float* pp[NP] = {p0, p1, p2, p3, p4};
    const size_t base = (size_t)t * (NH * HD) + (size_t)w * HD + lane * 4;

    float4 v[NP];
#pragma unroll
    for (int p = 0; p < NP; p++) v[p] = *reinterpret_cast<const float4*>(pp[p] + base);

    float vals[25];
#pragma unroll
    for (int p = 0; p < NP; p++) {
        vals[p]      = v[p].x + v[p].y + v[p].z + v[p].w;
        vals[5 + p]  = v[p].x * v[p].x + v[p].y * v[p].y + v[p].z * v[p].z + v[p].w * v[p].w;
        vals[10 + p] = fabsf(v[p].x) + fabsf(v[p].y) + fabsf(v[p].z) + fabsf(v[p].w);
    }
    {
        int k = 15;
#pragma unroll
        for (int p = 0; p < NP; p++)
#pragma unroll
            for (int q = p + 1; q < NP; q++)
                vals[k++] = v[p].x * v[q].x + v[p].y * v[q].y + v[p].z * v[q].z + v[p].w * v[q].w;
    }
#pragma unroll
    for (int i = 0; i < 25; i++) vals[i] = wredsum(vals[i]);

    if (lane == 0) {
        const float inv = 1.0f / 128.0f;
        float sq[NP];
#pragma unroll
        for (int p = 0; p < NP; p++) {
            float mean = vals[p] * inv;
            sq[p] = vals[5 + p];
            float l2 = sqrtf(sq[p]);
            float var = sq[p] * inv - mean * mean;
            float am  = vals[10 + p] * inv;
            float* s = gate + w * (NP * 4) + p * 4;
            s[0] = tf32r(mean); s[1] = tf32r(var); s[2] = tf32r(am); s[3] = tf32r(l2);
            gate[320 + w * NP + p] = tf32r(l2);
        }
        int kk = 0;
#pragma unroll
        for (int p = 0; p < NP; p++)
#pragma unroll
            for (int q = p + 1; q < NP; q++) {
                float d2 = sq[p] + sq[q] - 2.0f * vals[15 + kk];
                gate[400 + w * 10 + kk] = tf32r(sqrtf(fmaxf(d2, 0.0f)));
                kk++;
            }
    }
}

// ---------------------------------------------------------------------------
// Weight repacks (tf32-rounded; W1 zero-padded in K).
// ---------------------------------------------------------------------------
__global__ void pack_w1_kernel(const float* __restrict__ W1)
{
    const int idx = blockIdx.x * 256 + threadIdx.x;
    const int total = GATE_HID * (GATE_IN_PAD / 4);
    if (idx >= total) return;
    const int row = idx / (GATE_IN_PAD / 4);
    const int c4  = idx % (GATE_IN_PAD / 4);
    float4 v = {0.f, 0.f, 0.f, 0.f};
    if (c4 < GATE_IN / 4)
        v = reinterpret_cast<const float4*>(W1 + (size_t)row * GATE_IN)[c4];
    v.x = tf32r(v.x); v.y = tf32r(v.y); v.z = tf32r(v.z); v.w = tf32r(v.w);
    reinterpret_cast<float4*>(g_w1p + (size_t)row * GATE_IN_PAD)[c4] = v;
}

__global__ void pack_w2_kernel(const float* __restrict__ W2)
{
    const int idx = blockIdx.x * 256 + threadIdx.x;
    const int total = OUT_DIM * (GATE_HID / 4);
    if (idx >= total) return;
    float4 v = reinterpret_cast<const float4*>(W2)[idx];
    v.x = tf32r(v.x); v.y = tf32r(v.y); v.z = tf32r(v.z); v.w = tf32r(v.w);
    reinterpret_cast<float4*>(g_w2p)[idx] = v;
}

// ---------------------------------------------------------------------------
// GEMM1 loaders / fragment helpers
// ---------------------------------------------------------------------------
__device__ __forceinline__ void g1_load(uint32_t stage_s,
                                        const float* __restrict__ hid,
                                        const float* __restrict__ st,
                                        const float* __restrict__ Bm,
                                        int k0, int tid)
{
    const uint32_t a_s = stage_s;
    const uint32_t b_s = stage_s + G1_A_FLOATS * 4;
    const float* asrc;
    int astride, ak;
    if (k0 < HIDDEN) { asrc = hid; astride = HIDDEN; ak = k0; }
    else             { asrc = st;  astride = STAT_W; ak = k0 - HIDDEN; }
#pragma unroll
    for (int j = 0; j < 4; j++) {                 // A: 128 rows * 8 f4 = 1024
        const int idx = tid + j * 256;
        const int m  = idx >> 3;
        const int ks = (idx & 7) << 2;
        cp_async16(a_s + (uint32_t)(m * SM_STRIDE + ks) * 4,
                   asrc + (size_t)m * astride + ak + ks);
    }
#pragma unroll
    for (int j = 0; j < 8; j++) {                 // B: 256 rows * 8 f4 = 2048
        const int idx = tid + j * 256;
        const int m  = idx >> 3;
        const int ks = (idx & 7) << 2;
        cp_async16(b_s + (uint32_t)(m * SM_STRIDE + ks) * 4,
                   Bm + (size_t)m * GATE_IN_PAD + k0 + ks);
    }
}

__device__ __forceinline__ void g1_frags(const float* __restrict__ as,
                                         const float* __restrict__ bs,
                                         int wm, int wn, int g, int t, int kk,
                                         uint32_t a[4][4], uint32_t b[8][2])
{
#pragma unroll
    for (int mi = 0; mi < 4; mi++) {
        const float* r0 = as + (wm + mi * 16 + g) * SM_STRIDE + kk;
        const float* r1 = as + (wm + mi * 16 + g + 8) * SM_STRIDE + kk;
        a[mi][0] = __float_as_uint(r0[t]);
        a[mi][1] = __float_as_uint(r1[t]);
        a[mi][2] = __float_as_uint(r0[t + 4]);
        a[mi][3] = __float_as_uint(r1[t + 4]);
    }
#pragma unroll
    for (int nj = 0; nj < 8; nj++) {
        const float* br = bs + (wn + nj * 8 + g) * SM_STRIDE + kk;
        b[nj][0] = __float_as_uint(br[t]);
        b[nj][1] = __float_as_uint(br[t + 4]);
    }
}

// ---------------------------------------------------------------------------
// Kernel B: GEMM1 via mma.sync tf32. CTA 128x256, 8 warps (warp 64x64),
// 3-stage cp.async + explicit per-k-step fragment double buffering.
// ---------------------------------------------------------------------------
__global__ void __launch_bounds__(256, 1) gemm1_mma_kernel(const float* __restrict__ hidden,
                                                           const float* __restrict__ b1)
{
    extern __shared__ float smem[];
    const uint32_t s0 = smem_u32(smem);

    const int tid  = threadIdx.x;
    const int wid  = tid >> 5, lane = tid & 31;
    const int wm   = (wid & 1) * 64;
    const int wn   = (wid >> 1) * 64;
    const int g    = lane >> 2;
    const int t    = lane & 3;

    const float* hid = hidden  + (size_t)blockIdx.y * 128 * HIDDEN;
    const float* st  = g_stats + (size_t)blockIdx.y * 128 * STAT_W;
    const float* Bm  = g_w1p   + (size_t)blockIdx.x * 256 * GATE_IN_PAD;

    float acc[4][8][4];
#pragma unroll
    for (int i = 0; i < 4; i++)
#pragma unroll
        for (int j = 0; j < 8; j++)
#pragma unroll
            for (int r = 0; r < 4; r++) acc[i][j][r] = 0.0f;

    // prologue: chunks 0,1 -> stages 0,1
    g1_load(s0, hid, st, Bm, 0, tid);
    asm volatile("cp.async.commit_group;" ::: "memory");
    g1_load(s0 + (uint32_t)G1_STAGE_F * 4, hid, st, Bm, KCHUNK, tid);
    asm volatile("cp.async.commit_group;" ::: "memory");

    int stage_rd = 0;
    for (int i = 0; i < NCHUNK; i++) {
        if (i + 2 < NCHUNK) {
            const int ws = (i + 2) % 3;
            g1_load(s0 + (uint32_t)(ws * G1_STAGE_F) * 4, hid, st, Bm,
                    (i + 2) * KCHUNK, tid);
        }
        asm volatile("cp.async.commit_group;" ::: "memory");
        asm volatile("cp.async.wait_group 2;" ::: "memory");
        __syncthreads();

        const float* as = smem + stage_rd * G1_STAGE_F;
        const float* bs = as + G1_A_FLOATS;

        uint32_t a[2][4][4], b[2][8][2];
        g1_frags(as, bs, wm, wn, g, t, 0, a[0], b[0]);
#pragma unroll
        for (int ks = 0; ks < KCHUNK / 8; ks++) {
            const int cur = ks & 1, nxt = cur ^ 1;
            if (ks + 1 < KCHUNK / 8)
                g1_frags(as, bs, wm, wn, g, t, (ks + 1) * 8, a[nxt], b[nxt]);
#pragma unroll
            for (int mi = 0; mi < 4; mi++)
#pragma unroll
                for (int nj = 0; nj < 8; nj++)
                    mma_tf32_16x8x8(acc[mi][nj],
                                    a[cur][mi][0], a[cur][mi][1],
                                    a[cur][mi][2], a[cur][mi][3],
                                    b[cur][nj][0], b[cur][nj][1]);
        }
        __syncthreads();
        stage_rd = stage_rd + 1 == 3 ? 0 : stage_rd + 1;
    }

    // epilogue: bias + exact GELU, tf32-rounded -> g_h
    const size_t row_base = (size_t)blockIdx.y * 128 + wm + g;
    const int    col_base = blockIdx.x * 256 + wn + 2 * t;
#pragma unroll
    for (int nj = 0; nj < 8; nj++) {
        const int gc = col_base + nj * 8;
        const float2 bb = *reinterpret_cast<const float2*>(b1 + gc);
#pragma unroll
        for (int mi = 0; mi < 4; mi++) {
            const size_t r0 = row_base + mi * 16;
            float2 o0, o1;
            o0.x = tf32r(gelu(acc[mi][nj][0] + bb.x));
            o0.y = tf32r(gelu(acc[mi][nj][1] + bb.y));
            o1.x = tf32r(gelu(acc[mi][nj][2] + bb.x));
            o1.y = tf32r(gelu(acc[mi][nj][3] + bb.y));
            *reinterpret_cast<float2*>(g_h + r0 * GATE_HID + gc)       = o0;
            *reinterpret_cast<float2*>(g_h + (r0 + 8) * GATE_HID + gc) = o1;
        }
    }
}

// ---------------------------------------------------------------------------
// Kernel C: GEMM2 via mma.sync tf32 + fused bias/softmax/clip/renorm.
// ---------------------------------------------------------------------------
__global__ void __launch_bounds__(256) gemm2_mma_kernel(
    const float* __restrict__ b2, const float* __restrict__ log_temp)
{
    extern __shared__ float smem[];
    const uint32_t s0 = smem_u32(smem);

    const int tid  = threadIdx.x;
    const int wid  = tid >> 5, lane = tid & 31;
    const int mw   = wid >> 1;
    const int nw   = wid & 1;
    const int g    = lane >> 2;
    const int t    = lane & 3;

    const int tbase = blockIdx.x * 64;
    const float* A = g_h + (size_t)tbase * GATE_HID;

    float acc[5][4];
#pragma unroll
    for (int j = 0; j < 5; j++)
#pragma unroll
        for (int r = 0; r < 4; r++) acc[j][r] = 0.0f;

    const uint32_t aoff[2] = {0u, (uint32_t)G2_A_FLOATS * 4};
    const uint32_t boff[2] = {(uint32_t)(2 * G2_A_FLOATS) * 4,
                              (uint32_t)(2 * G2_A_FLOATS + G2_B_FLOATS) * 4};

    {
#pragma unroll
        for (int j = 0; j < 2; j++) {
            const int idx = tid + j * 256;
            const int m = idx >> 3, ks = (idx & 7) << 2;
            cp_async16(s0 + aoff[0] + (uint32_t)(m * SM_STRIDE + ks) * 4,
                       A + (size_t)m * GATE_HID + ks);
        }
#pragma unroll
        for (int j = 0; j < 3; j++) {
            const int idx = tid + j * 256;
            if (idx < 640) {
                const int m = idx >> 3, ks = (idx & 7) << 2;
                cp_async16(s0 + boff[0] + (uint32_t)(m * SM_STRIDE + ks) * 4,
                           g_w2p + (size_t)m * GATE_HID + ks);
            }
        }
        asm volatile("cp.async.commit_group;" ::: "memory");
    }

    for (int i = 0; i < G2_NCH; i++) {
        const int s = i & 1;
        if (i + 1 < G2_NCH) {
            const int ns = (i + 1) & 1;
            const int k0 = (i + 1) * G2_KC;
#pragma unroll
            for (int j = 0; j < 2; j++) {
                const int idx = tid + j * 256;
                const int m = idx >> 3, ks = (idx & 7) << 2;
                cp_async16(s0 + aoff[ns] + (uint32_t)(m * SM_STRIDE + ks) * 4,
                           A + (size_t)m * GATE_HID + k0 + ks);
            }
#pragma unroll
            for (int j = 0; j < 3; j++) {
                const int idx = tid + j * 256;
                if (idx < 640) {
                    const int m = idx >> 3, ks = (idx & 7) << 2;
                    cp_async16(s0 + boff[ns] + (uint32_t)(m * SM_STRIDE + ks) * 4,
                               g_w2p + (size_t)m * GATE_HID + k0 + ks);
                }
            }
        }
        asm volatile("cp.async.commit_group;" ::: "memory");
        if (i + 1 < G2_NCH) asm volatile("cp.async.wait_group 1;" ::: "memory");
        else                asm volatile("cp.async.wait_group 0;" ::: "memory");
        __syncthreads();

        const float* as = smem + (s ? G2_A_FLOATS : 0);
        const float* bs = smem + 2 * G2_A_FLOATS + (s ? G2_B_FLOATS : 0);

#pragma unroll
        for (int kk = 0; kk < G2_KC; kk += 8) {
            const float* r0 = as + (mw * 16 + g) * SM_STRIDE + kk;
            const float* r1 = as + (mw * 16 + g + 8) * SM_STRIDE + kk;
            uint32_t a0 = __float_as_uint(r0[t]);
            uint32_t a1 = __float_as_uint(r1[t]);
            uint32_t a2 = __float_as_uint(r0[t + 4]);
            uint32_t a3 = __float_as_uint(r1[t + 4]);
#pragma unroll
            for (int nj = 0; nj < 5; nj++) {
                const float* br = bs + (nw * 40 + nj * 8 + g) * SM_STRIDE + kk;
                mma_tf32_16x8x8(acc[nj], a0, a1, a2, a3,
                                __float_as_uint(br[t]), __float_as_uint(br[t + 4]));
            }
        }
        __syncthreads();
    }

    float* lg = smem;
    {
        const int r0 = mw * 16 + g;
        const int c0 = nw * 40 + 2 * t;
#pragma unroll
        for (int nj = 0; nj < 5; nj++) {
            const int c = c0 + nj * 8;
            lg[r0 * OUT_DIM + c]            = acc[nj][0];
            lg[r0 * OUT_DIM + c + 1]        = acc[nj][1];
            lg[(r0 + 8) * OUT_DIM + c]      = acc[nj][2];
            lg[(r0 + 8) * OUT_DIM + c + 1]  = acc[nj][3];
        }
    }
    __syncthreads();

#pragma unroll
    for (int it = 0; it < 4; it++) {
        const int idx = tid + it * 256;
        const int tt = idx >> 4, h = idx & 15;
        const float invt = expf(-log_temp[h]);
        float l[NP], mx = -1e30f;
#pragma unroll
        for (int p = 0; p < NP; p++) {
            l[p] = (lg[tt * OUT_DIM + h * NP + p] + __ldg(b2 + h * NP + p)) * invt;
            mx = fmaxf(mx, l[p]);
        }
        float e[NP], se = 0.f;
#pragma unroll
        for (int p = 0; p < NP; p++) { e[p] = expf(l[p] - mx); se += e[p]; }
        const float ise = 1.0f / se;
        float pr[NP], s2s = 0.f;
#pragma unroll
        for (int p = 0; p < NP; p++) { pr[p] = fmaxf(e[p] * ise, 0.02f); s2s += pr[p]; }
        const float is2 = 1.0f / s2s;
        float* dst = g_probs + (size_t)(tbase + tt) * OUT_DIM + h * NP;
#pragma unroll
        for (int p = 0; p < NP; p++) dst[p] = pr[p] * is2;
    }
}

// ---------------------------------------------------------------------------
// Kernel D: weighted path combine.
// ---------------------------------------------------------------------------
__global__ void output_kernel(
    const float* __restrict__ p0, const float* __restrict__ p1,
    const float* __restrict__ p2, const float* __restrict__ p3,
    const float* __restrict__ p4, float* __restrict__ out, int n4)
{
    const int v = blockIdx.x * blockDim.x + threadIdx.x;
    if (v >= n4) return;
    const int t = v >> 9;
    const int h = (v >> 5) & 15;
    const float* pb = g_probs + (size_t)t * OUT_DIM + h * NP;
    const float w0 = pb[0], w1 = pb[1], w2 = pb[2], w3 = pb[3], w4 = pb[4];
    const float4 a0 = reinterpret_cast<const float4*>(p0)[v];
    const float4 a1 = reinterpret_cast<const float4*>(p1)[v];
    const float4 a2 = reinterpret_cast<const float4*>(p2)[v];
    const float4 a3 = reinterpret_cast<const float4*>(p3)[v];
    const float4 a4 = reinterpret_cast<const float4*>(p4)[v];
    float4 o;
    o.x = a0.x * w0 + a1.x * w1 + a2.x * w2 + a3.x * w3 + a4.x * w4;
    o.y = a0.y * w0 + a1.y * w1 + a2.y * w2 + a3.y * w3 + a4.y * w4;
    o.z = a0.z * w0 + a1.z * w1 + a2.z * w2 + a3.z * w3 + a4.z * w4;
    o.w = a0.w * w0 + a1.w * w1 + a2.w * w2 + a3.w * w3 + a4.w * w4;
    reinterpret_cast<float4*>(out)[v] = o;
}

__global__ void zero_tail_kernel(float* out, int start, int total)
{
    const int i = start + blockIdx.x * blockDim.x + threadIdx.x;
    if (i < total) out[i] = 0.0f;
}

// ---------------------------------------------------------------------------
extern "C" void kernel_launch(void* const* d_in, const int* in_sizes, int n_in,
                              void* d_out, int out_size)
{
    const float* hidden = (const float*)d_in[0];
    const float* p0 = (const float*)d_in[1];
    const float* p1 = (const float*)d_in[2];
    const float* p2 = (const float*)d_in[3];
    const float* p3 = (const float*)d_in[4];
    const float* p4 = (const float*)d_in[5];
    const float* W1 = (const float*)d_in[6];
    const float* b1 = (const float*)d_in[7];
    const float* W2 = (const float*)d_in[8];
    const float* b2 = (const float*)d_in[9];
    const float* lt = (const float*)d_in[10];

    const int NT = in_sizes[0] / HIDDEN;   // 8192

    static int smem_set = 0;
    if (!smem_set) {
        cudaFuncSetAttribute(gemm1_mma_kernel,
                             cudaFuncAttributeMaxDynamicSharedMemorySize, GEMM1_SMEM);
        cudaFuncSetAttribute(gemm2_mma_kernel,
                             cudaFuncAttributeMaxDynamicSharedMemorySize, GEMM2_SMEM);
        smem_set = 1;
    }

    {
        const int t1 = GATE_HID * (GATE_IN_PAD / 4);
        pack_w1_kernel<<<(t1 + 255) / 256, 256>>>(W1);
        const int t2 = OUT_DIM * (GATE_HID / 4);
        pack_w2_kernel<<<(t2 + 255) / 256, 256>>>(W2);
    }
    stats_kernel<<<NT, 512>>>(p0, p1, p2, p3, p4);

    dim3 g1(GATE_HID / 256, NT / 128);   // (4, 64)
    gemm1_mma_kernel<<<g1, 256, GEMM1_SMEM>>>(hidden, b1);

    gemm2_mma_kernel<<<NT / 64, 256, GEMM2_SMEM>>>(b2, lt);

    const int n4 = NT * (NH * HD) / 4;
    output_kernel<<<(n4 + 255) / 256, 256>>>(p0, p1, p2, p3, p4, (float*)d_out, n4);

    const int nout = NT * NH * HD;
    if (out_size > nout) {
        const int extra = out_size - nout;
        zero_tail_kernel<<<(extra + 255) / 256, 256>>>((float*)d_out, nout, out_size);
    }
}

// round 8
// speedup vs baseline: 1.4808x; 1.4226x over previous
#include <cuda_runtime.h>
#include <cuda_fp16.h>
#include <cstdint>
#include <math.h>

#define HIDDEN      2048
#define GATE_IN     2608
#define GATE_IN_PAD 2624        // 41 * 64
#define STAT_W      576         // 560 data + 16 zero pad (9 * 64)
#define GATE_HID    1024
#define NH          16
#define HD          128
#define NP          5
#define OUT_DIM     80
#define MAX_NT      8192

// GEMM1: CTA 128x256, 8 warps (2M x 4N, warp 64x64), fp16 m16n8k16
#define KCH         64                         // halves per K chunk (128 B)
#define NCHUNK      (GATE_IN_PAD / KCH)        // 41
#define STRH        72                         // padded halves per row
#define G1_A_H      (128 * STRH)               // 9216 halves
#define G1_B_H      (256 * STRH)               // 18432 halves
#define G1_STAGE_B  ((G1_A_H + G1_B_H) * 2)    // 55296 B
#define GEMM1_SMEM  (3 * G1_STAGE_B)           // 165888 B

// GEMM2: CTA 64(M) x 80(N), 8 warps (4M x 2N, warp 16x40), K=1024
#define G2_NCH      (GATE_HID / KCH)           // 16
#define G2_A_H      (64 * STRH)                // 4608 halves
#define G2_B_H      (80 * STRH)                // 5760 halves
#define GEMM2_SMEM  (2 * (G2_A_H + G2_B_H) * 2)  // 41472 B

// Static scratch (all fp16 operands)
__device__ __half g_hid_h[(size_t)MAX_NT * HIDDEN];
__device__ __half g_stats[(size_t)MAX_NT * STAT_W];
__device__ __half g_w1p[(size_t)GATE_HID * GATE_IN_PAD];
__device__ __half g_w2p[(size_t)OUT_DIM * GATE_HID];
__device__ __half g_h[(size_t)MAX_NT * GATE_HID];
__device__ float  g_probs[(size_t)MAX_NT * OUT_DIM];

// ---------------------------------------------------------------------------
// helpers
// ---------------------------------------------------------------------------
__device__ __forceinline__ float wredsum(float v) {
#pragma unroll
    for (int o = 16; o; o >>= 1) v += __shfl_xor_sync(0xffffffffu, v, o);
    return v;
}
__device__ __forceinline__ void cp_async16(uint32_t dst, const void* src) {
    asm volatile("cp.async.cg.shared.global [%0], [%1], 16;" :: "r"(dst), "l"(src));
}
__device__ __forceinline__ uint32_t smem_u32(const void* p) {
    uint32_t a;
    asm("{ .reg .u64 t; cvta.to.shared.u64 t, %1; cvt.u32.u64 %0, t; }" : "=r"(a) : "l"(p));
    return a;
}
__device__ __forceinline__ float gelu(float x) {
    return 0.5f * x * (1.0f + erff(x * 0.70710678118654752f));
}
// PTX m16n8k16 f16 (g=lane>>2, t=lane&3), fp32 accum:
//   a0={A[g][2t],A[g][2t+1]}       a1={A[g+8][2t],A[g+8][2t+1]}
//   a2={A[g][2t+8],A[g][2t+9]}     a3={A[g+8][2t+8],A[g+8][2t+9]}
//   b0={B[2t][g],B[2t+1][g]}       b1={B[2t+8][g],B[2t+9][g]}   (col-major KxN)
//   c0=(g,2t) c1=(g,2t+1) c2=(g+8,2t) c3=(g+8,2t+1)
__device__ __forceinline__ void mma_f16_16x8x16(float c[4],
                                                uint32_t a0, uint32_t a1,
                                                uint32_t a2, uint32_t a3,
                                                uint32_t b0, uint32_t b1) {
    asm("mma.sync.aligned.m16n8k16.row.col.f32.f16.f16.f32 "
        "{%0,%1,%2,%3}, {%4,%5,%6,%7}, {%8,%9}, {%0,%1,%2,%3};"
        : "+f"(c[0]), "+f"(c[1]), "+f"(c[2]), "+f"(c[3])
        : "r"(a0), "r"(a1), "r"(a2), "r"(a3), "r"(b0), "r"(b1));
}

// ---------------------------------------------------------------------------
// Kernel A: path stats -> g_stats[t][576] (fp16) + hidden -> g_hid_h (fp16).
// stats[h][p][4] at 0, norms[h][p] at 320, pairwise[h][10] at 400, zeros 560+.
// ---------------------------------------------------------------------------
__global__ void __launch_bounds__(512) stats_kernel(
    const float* __restrict__ hidden,
    const float* __restrict__ p0, const float* __restrict__ p1,
    const float* __restrict__ p2, const float* __restrict__ p3,
    const float* __restrict__ p4)
{
    const int t   = blockIdx.x;
    const int tid = threadIdx.x;
    __half* gate = g_stats + (size_t)t * STAT_W;

    // hidden fp32 -> fp16 (512 thr * 4 elems)
    {
        const float4 hv = (reinterpret_cast<const float4*>(hidden) + (size_t)t * (HIDDEN / 4))[tid];
        __half2 h0 = __floats2half2_rn(hv.x, hv.y);
        __half2 h1 = __floats2half2_rn(hv.z, hv.w);
        uint2 u;
        u.x = *reinterpret_cast<uint32_t*>(&h0);
        u.y = *reinterpret_cast<uint32_t*>(&h1);
        reinterpret_cast<uint2*>(g_hid_h + (size_t)t * HIDDEN)[tid] = u;
    }
    if (tid < 4) {   // zero pad halves [560:576)
        uint2 z = {0u, 0u};
        reinterpret_cast<uint2*>(gate + 560)[tid] = z;
    }

    const int w = tid >> 5, lane = tid & 31;
    const float* pp[NP] = {p0, p1, p2, p3, p4};
    const size_t base = (size_t)t * (NH * HD) + (size_t)w * HD + lane * 4;

    float4 v[NP];
#pragma unroll
    for (int p = 0; p < NP; p++) v[p] = *reinterpret_cast<const float4*>(pp[p] + base);

    float vals[25];
#pragma unroll
    for (int p = 0; p < NP; p++) {
        vals[p]      = v[p].x + v[p].y + v[p].z + v[p].w;
        vals[5 + p]  = v[p].x * v[p].x + v[p].y * v[p].y + v[p].z * v[p].z + v[p].w * v[p].w;
        vals[10 + p] = fabsf(v[p].x) + fabsf(v[p].y) + fabsf(v[p].z) + fabsf(v[p].w);
    }
    {
        int k = 15;
#pragma unroll
        for (int p = 0; p < NP; p++)
#pragma unroll
            for (int q = p + 1; q < NP; q++)
                vals[k++] = v[p].x * v[q].x + v[p].y * v[q].y + v[p].z * v[q].z + v[p].w * v[q].w;
    }
#pragma unroll
    for (int i = 0; i < 25; i++) vals[i] = wredsum(vals[i]);

    if (lane == 0) {
        const float inv = 1.0f / 128.0f;
        float sq[NP];
#pragma unroll
        for (int p = 0; p < NP; p++) {
            float mean = vals[p] * inv;
            sq[p] = vals[5 + p];
            float l2 = sqrtf(sq[p]);
            float var = sq[p] * inv - mean * mean;
            float am  = vals[10 + p] * inv;
            __half* s = gate + w * (NP * 4) + p * 4;
            s[0] = __float2half_rn(mean); s[1] = __float2half_rn(var);
            s[2] = __float2half_rn(am);   s[3] = __float2half_rn(l2);
            gate[320 + w * NP + p] = __float2half_rn(l2);
        }
        int kk = 0;
#pragma unroll
        for (int p = 0; p < NP; p++)
#pragma unroll
            for (int q = p + 1; q < NP; q++) {
                float d2 = sq[p] + sq[q] - 2.0f * vals[15 + kk];
                gate[400 + w * 10 + kk] = __float2half_rn(sqrtf(fmaxf(d2, 0.0f)));
                kk++;
            }
    }
}

// ---------------------------------------------------------------------------
// Weight repacks -> fp16 (W1 zero-padded in K).
// ---------------------------------------------------------------------------
__global__ void pack_w1_kernel(const float* __restrict__ W1)
{
    const int idx = blockIdx.x * 256 + threadIdx.x;     // 4-half group
    const int total = GATE_HID * (GATE_IN_PAD / 4);
    if (idx >= total) return;
    const int row = idx / (GATE_IN_PAD / 4);
    const int c4  = idx % (GATE_IN_PAD / 4);
    float4 v = {0.f, 0.f, 0.f, 0.f};
    if (c4 < GATE_IN / 4)
        v = reinterpret_cast<const float4*>(W1 + (size_t)row * GATE_IN)[c4];
    __half2 h0 = __floats2half2_rn(v.x, v.y);
    __half2 h1 = __floats2half2_rn(v.z, v.w);
    uint2 u;
    u.x = *reinterpret_cast<uint32_t*>(&h0);
    u.y = *reinterpret_cast<uint32_t*>(&h1);
    reinterpret_cast<uint2*>(g_w1p + (size_t)row * GATE_IN_PAD)[c4] = u;
}

__global__ void pack_w2_kernel(const float* __restrict__ W2)
{
    const int idx = blockIdx.x * 256 + threadIdx.x;
    const int total = OUT_DIM * (GATE_HID / 4);
    if (idx >= total) return;
    float4 v = reinterpret_cast<const float4*>(W2)[idx];
    __half2 h0 = __floats2half2_rn(v.x, v.y);
    __half2 h1 = __floats2half2_rn(v.z, v.w);
    uint2 u;
    u.x = *reinterpret_cast<uint32_t*>(&h0);
    u.y = *reinterpret_cast<uint32_t*>(&h1);
    reinterpret_cast<uint2*>(g_w2p)[idx] = u;
}

// ---------------------------------------------------------------------------
// Kernel B: GEMM1 fp16 mma. h = fp16(GELU(gate @ W1p^T + b1))
// A on the fly: chunks 0..31 from g_hid_h, 32..40 from g_stats.
// ---------------------------------------------------------------------------
__device__ __forceinline__ void g1_load(uint32_t stage_s,
                                        const __half* __restrict__ hid,
                                        const __half* __restrict__ st,
                                        const __half* __restrict__ Bm,
                                        int k0, int tid)
{
    const uint32_t a_s = stage_s;
    const uint32_t b_s = stage_s + G1_A_H * 2;
    const __half* asrc;
    int astride, ak;
    if (k0 < HIDDEN) { asrc = hid; astride = HIDDEN; ak = k0; }
    else             { asrc = st;  astride = STAT_W; ak = k0 - HIDDEN; }
#pragma unroll
    for (int j = 0; j < 4; j++) {      // A: 128 rows * 8 segs (8 halves each)
        const int idx = tid + j * 256;
        const int m  = idx >> 3;
        const int ks = (idx & 7) << 3;
        cp_async16(a_s + (uint32_t)(m * STRH + ks) * 2,
                   asrc + (size_t)m * astride + ak + ks);
    }
#pragma unroll
    for (int j = 0; j < 8; j++) {      // B: 256 rows * 8 segs
        const int idx = tid + j * 256;
        const int m  = idx >> 3;
        const int ks = (idx & 7) << 3;
        cp_async16(b_s + (uint32_t)(m * STRH + ks) * 2,
                   Bm + (size_t)m * GATE_IN_PAD + k0 + ks);
    }
}

__global__ void __launch_bounds__(256, 1) gemm1_mma_kernel(const float* __restrict__ b1)
{
    extern __shared__ __half smem[];
    const uint32_t s0 = smem_u32(smem);

    const int tid  = threadIdx.x;
    const int wid  = tid >> 5, lane = tid & 31;
    const int wm   = (wid & 1) * 64;
    const int wn   = (wid >> 1) * 64;
    const int g    = lane >> 2;
    const int t2   = (lane & 3) * 2;    // 2t

    const __half* hid = g_hid_h + (size_t)blockIdx.y * 128 * HIDDEN;
    const __half* st  = g_stats + (size_t)blockIdx.y * 128 * STAT_W;
    const __half* Bm  = g_w1p   + (size_t)blockIdx.x * 256 * GATE_IN_PAD;

    float acc[4][8][4];
#pragma unroll
    for (int i = 0; i < 4; i++)
#pragma unroll
        for (int j = 0; j < 8; j++)
#pragma unroll
            for (int r = 0; r < 4; r++) acc[i][j][r] = 0.0f;

    g1_load(s0, hid, st, Bm, 0, tid);
    asm volatile("cp.async.commit_group;" ::: "memory");
    g1_load(s0 + G1_STAGE_B, hid, st, Bm, KCH, tid);
    asm volatile("cp.async.commit_group;" ::: "memory");

    int stage_rd = 0;
    for (int i = 0; i < NCHUNK; i++) {
        if (i + 2 < NCHUNK) {
            const int ws = (i + 2) % 3;
            g1_load(s0 + (uint32_t)ws * G1_STAGE_B, hid, st, Bm, (i + 2) * KCH, tid);
        }
        asm volatile("cp.async.commit_group;" ::: "memory");
        asm volatile("cp.async.wait_group 2;" ::: "memory");
        __syncthreads();

        const __half* as = smem + stage_rd * (G1_STAGE_B / 2);
        const __half* bs = as + G1_A_H;

#pragma unroll
        for (int kk = 0; kk < KCH; kk += 16) {
            uint32_t a[4][4];
#pragma unroll
            for (int mi = 0; mi < 4; mi++) {
                const __half* r0 = as + (wm + mi * 16 + g) * STRH + kk + t2;
                const __half* r1 = as + (wm + mi * 16 + g + 8) * STRH + kk + t2;
                a[mi][0] = *reinterpret_cast<const uint32_t*>(r0);
                a[mi][1] = *reinterpret_cast<const uint32_t*>(r1);
                a[mi][2] = *reinterpret_cast<const uint32_t*>(r0 + 8);
                a[mi][3] = *reinterpret_cast<const uint32_t*>(r1 + 8);
            }
            uint32_t b[8][2];
#pragma unroll
            for (int nj = 0; nj < 8; nj++) {
                const __half* br = bs + (wn + nj * 8 + g) * STRH + kk + t2;
                b[nj][0] = *reinterpret_cast<const uint32_t*>(br);
                b[nj][1] = *reinterpret_cast<const uint32_t*>(br + 8);
            }
#pragma unroll
            for (int mi = 0; mi < 4; mi++)
#pragma unroll
                for (int nj = 0; nj < 8; nj++)
                    mma_f16_16x8x16(acc[mi][nj], a[mi][0], a[mi][1], a[mi][2], a[mi][3],
                                    b[nj][0], b[nj][1]);
        }
        __syncthreads();
        stage_rd = stage_rd + 1 == 3 ? 0 : stage_rd + 1;
    }

    // epilogue: bias + exact GELU -> fp16 g_h (c0,c1 adjacent cols -> half2)
    const size_t row_base = (size_t)blockIdx.y * 128 + wm + g;
    const int    col_base = blockIdx.x * 256 + wn + t2;
#pragma unroll
    for (int nj = 0; nj < 8; nj++) {
        const int gc = col_base + nj * 8;
        const float2 bb = *reinterpret_cast<const float2*>(b1 + gc);
#pragma unroll
        for (int mi = 0; mi < 4; mi++) {
            const size_t r0 = row_base + mi * 16;
            __half2 o0 = __floats2half2_rn(gelu(acc[mi][nj][0] + bb.x),
                                           gelu(acc[mi][nj][1] + bb.y));
            __half2 o1 = __floats2half2_rn(gelu(acc[mi][nj][2] + bb.x),
                                           gelu(acc[mi][nj][3] + bb.y));
            *reinterpret_cast<__half2*>(g_h + r0 * GATE_HID + gc)       = o0;
            *reinterpret_cast<__half2*>(g_h + (r0 + 8) * GATE_HID + gc) = o1;
        }
    }
}

// ---------------------------------------------------------------------------
// Kernel C: GEMM2 fp16 mma + fused bias/softmax/clip/renorm.
// ---------------------------------------------------------------------------
__global__ void __launch_bounds__(256) gemm2_mma_kernel(
    const float* __restrict__ b2, const float* __restrict__ log_temp)
{
    extern __shared__ __half smem[];
    const uint32_t s0 = smem_u32(smem);

    const int tid  = threadIdx.x;
    const int wid  = tid >> 5, lane = tid & 31;
    const int mw   = wid >> 1;
    const int nw   = wid & 1;
    const int g    = lane >> 2;
    const int t2   = (lane & 3) * 2;

    const int tbase = blockIdx.x * 64;
    const __half* A = g_h + (size_t)tbase * GATE_HID;

    float acc[5][4];
#pragma unroll
    for (int j = 0; j < 5; j++)
#pragma unroll
        for (int r = 0; r < 4; r++) acc[j][r] = 0.0f;

    const uint32_t aoff[2] = {0u, (uint32_t)G2_A_H * 2};
    const uint32_t boff[2] = {(uint32_t)(2 * G2_A_H) * 2,
                              (uint32_t)(2 * G2_A_H + G2_B_H) * 2};

    // prologue
    {
#pragma unroll
        for (int j = 0; j < 2; j++) {          // A: 64 rows * 8 segs = 512
            const int idx = tid + j * 256;
            const int m = idx >> 3, ks = (idx & 7) << 3;
            cp_async16(s0 + aoff[0] + (uint32_t)(m * STRH + ks) * 2,
                       A + (size_t)m * GATE_HID + ks);
        }
#pragma unroll
        for (int j = 0; j < 3; j++) {          // B: 80 rows * 8 segs = 640
            const int idx = tid + j * 256;
            if (idx < 640) {
                const int m = idx >> 3, ks = (idx & 7) << 3;
                cp_async16(s0 + boff[0] + (uint32_t)(m * STRH + ks) * 2,
                           g_w2p + (size_t)m * GATE_HID + ks);
            }
        }
        asm volatile("cp.async.commit_group;" ::: "memory");
    }

    for (int i = 0; i < G2_NCH; i++) {
        const int s = i & 1;
        if (i + 1 < G2_NCH) {
            const int ns = (i + 1) & 1;
            const int k0 = (i + 1) * KCH;
#pragma unroll
            for (int j = 0; j < 2; j++) {
                const int idx = tid + j * 256;
                const int m = idx >> 3, ks = (idx & 7) << 3;
                cp_async16(s0 + aoff[ns] + (uint32_t)(m * STRH + ks) * 2,
                           A + (size_t)m * GATE_HID + k0 + ks);
            }
#pragma unroll
            for (int j = 0; j < 3; j++) {
                const int idx = tid + j * 256;
                if (idx < 640) {
                    const int m = idx >> 3, ks = (idx & 7) << 3;
                    cp_async16(s0 + boff[ns] + (uint32_t)(m * STRH + ks) * 2,
                               g_w2p + (size_t)m * GATE_HID + k0 + ks);
                }
            }
        }
        asm volatile("cp.async.commit_group;" ::: "memory");
        if (i + 1 < G2_NCH) asm volatile("cp.async.wait_group 1;" ::: "memory");
        else                asm volatile("cp.async.wait_group 0;" ::: "memory");
        __syncthreads();

        const __half* as = smem + (s ? G2_A_H : 0);
        const __half* bs = smem + 2 * G2_A_H + (s ? G2_B_H : 0);

#pragma unroll
        for (int kk = 0; kk < KCH; kk += 16) {
            const __half* r0 = as + (mw * 16 + g) * STRH + kk + t2;
            const __half* r1 = as + (mw * 16 + g + 8) * STRH + kk + t2;
            uint32_t a0 = *reinterpret_cast<const uint32_t*>(r0);
            uint32_t a1 = *reinterpret_cast<const uint32_t*>(r1);
            uint32_t a2 = *reinterpret_cast<const uint32_t*>(r0 + 8);
            uint32_t a3 = *reinterpret_cast<const uint32_t*>(r1 + 8);
#pragma unroll
            for (int nj = 0; nj < 5; nj++) {
                const __half* br = bs + (nw * 40 + nj * 8 + g) * STRH + kk + t2;
                mma_f16_16x8x16(acc[nj], a0, a1, a2, a3,
                                *reinterpret_cast<const uint32_t*>(br),
                                *reinterpret_cast<const uint32_t*>(br + 8));
            }
        }
        __syncthreads();
    }

    // logits -> smem (fp32 view over the stage memory)
    float* lg = reinterpret_cast<float*>(smem);
    {
        const int r0 = mw * 16 + g;
        const int c0 = nw * 40 + t2;
#pragma unroll
        for (int nj = 0; nj < 5; nj++) {
            const int c = c0 + nj * 8;
            lg[r0 * OUT_DIM + c]            = acc[nj][0];
            lg[r0 * OUT_DIM + c + 1]        = acc[nj][1];
            lg[(r0 + 8) * OUT_DIM + c]      = acc[nj][2];
            lg[(r0 + 8) * OUT_DIM + c + 1]  = acc[nj][3];
        }
    }
    __syncthreads();

#pragma unroll
    for (int it = 0; it < 4; it++) {
        const int idx = tid + it * 256;
        const int tt = idx >> 4, h = idx & 15;
        const float invt = expf(-log_temp[h]);
        float l[NP], mx = -1e30f;
#pragma unroll
        for (int p = 0; p < NP; p++) {
            l[p] = (lg[tt * OUT_DIM + h * NP + p] + __ldg(b2 + h * NP + p)) * invt;
            mx = fmaxf(mx, l[p]);
        }
        float e[NP], se = 0.f;
#pragma unroll
        for (int p = 0; p < NP; p++) { e[p] = expf(l[p] - mx); se += e[p]; }
        const float ise = 1.0f / se;
        float pr[NP], s2s = 0.f;
#pragma unroll
        for (int p = 0; p < NP; p++) { pr[p] = fmaxf(e[p] * ise, 0.02f); s2s += pr[p]; }
        const float is2 = 1.0f / s2s;
        float* dst = g_probs + (size_t)(tbase + tt) * OUT_DIM + h * NP;
#pragma unroll
        for (int p = 0; p < NP; p++) dst[p] = pr[p] * is2;
    }
}

// ---------------------------------------------------------------------------
// Kernel D: weighted path combine.
// ---------------------------------------------------------------------------
__global__ void output_kernel(
    const float* __restrict__ p0, const float* __restrict__ p1,
    const float* __restrict__ p2, const float* __restrict__ p3,
    const float* __restrict__ p4, float* __restrict__ out, int n4)
{
    const int v = blockIdx.x * blockDim.x + threadIdx.x;
    if (v >= n4) return;
    const int t = v >> 9;
    const int h = (v >> 5) & 15;
    const float* pb = g_probs + (size_t)t * OUT_DIM + h * NP;
    const float w0 = pb[0], w1 = pb[1], w2 = pb[2], w3 = pb[3], w4 = pb[4];
    const float4 a0 = reinterpret_cast<const float4*>(p0)[v];
    const float4 a1 = reinterpret_cast<const float4*>(p1)[v];
    const float4 a2 = reinterpret_cast<const float4*>(p2)[v];
    const float4 a3 = reinterpret_cast<const float4*>(p3)[v];
    const float4 a4 = reinterpret_cast<const float4*>(p4)[v];
    float4 o;
    o.x = a0.x * w0 + a1.x * w1 + a2.x * w2 + a3.x * w3 + a4.x * w4;
    o.y = a0.y * w0 + a1.y * w1 + a2.y * w2 + a3.y * w3 + a4.y * w4;
    o.z = a0.z * w0 + a1.z * w1 + a2.z * w2 + a3.z * w3 + a4.z * w4;
    o.w = a0.w * w0 + a1.w * w1 + a2.w * w2 + a3.w * w3 + a4.w * w4;
    reinterpret_cast<float4*>(out)[v] = o;
}

__global__ void zero_tail_kernel(float* out, int start, int total)
{
    const int i = start + blockIdx.x * blockDim.x + threadIdx.x;
    if (i < total) out[i] = 0.0f;
}

// ---------------------------------------------------------------------------
extern "C" void kernel_launch(void* const* d_in, const int* in_sizes, int n_in,
                              void* d_out, int out_size)
{
    const float* hidden = (const float*)d_in[0];
    const float* p0 = (const float*)d_in[1];
    const float* p1 = (const float*)d_in[2];
    const float* p2 = (const float*)d_in[3];
    const float* p3 = (const float*)d_in[4];
    const float* p4 = (const float*)d_in[5];
    const float* W1 = (const float*)d_in[6];
    const float* b1 = (const float*)d_in[7];
    const float* W2 = (const float*)d_in[8];
    const float* b2 = (const float*)d_in[9];
    const float* lt = (const float*)d_in[10];

    const int NT = in_sizes[0] / HIDDEN;   // 8192

    static int smem_set = 0;
    if (!smem_set) {
        cudaFuncSetAttribute(gemm1_mma_kernel,
                             cudaFuncAttributeMaxDynamicSharedMemorySize, GEMM1_SMEM);
        cudaFuncSetAttribute(gemm2_mma_kernel,
                             cudaFuncAttributeMaxDynamicSharedMemorySize, GEMM2_SMEM);
        smem_set = 1;
    }

    {
        const int t1 = GATE_HID * (GATE_IN_PAD / 4);
        pack_w1_kernel<<<(t1 + 255) / 256, 256>>>(W1);
        const int t2 = OUT_DIM * (GATE_HID / 4);
        pack_w2_kernel<<<(t2 + 255) / 256, 256>>>(W2);
    }
    stats_kernel<<<NT, 512>>>(hidden, p0, p1, p2, p3, p4);

    dim3 g1(GATE_HID / 256, NT / 128);   // (4, 64)
    gemm1_mma_kernel<<<g1, 256, GEMM1_SMEM>>>(b1);

    gemm2_mma_kernel<<<NT / 64, 256, GEMM2_SMEM>>>(b2, lt);

    const int n4 = NT * (NH * HD) / 4;
    output_kernel<<<(n4 + 255) / 256, 256>>>(p0, p1, p2, p3, p4, (float*)d_out, n4);

    const int nout = NT * NH * HD;
    if (out_size > nout) {
        const int extra = out_size - nout;
        zero_tail_kernel<<<(extra + 255) / 256, 256>>>((float*)d_out, nout, out_size);
    }
}

// round 9
// speedup vs baseline: 1.4940x; 1.0089x over previous
#include <cuda_runtime.h>
#include <cuda_fp16.h>
#include <cstdint>
#include <math.h>

#define HIDDEN      2048
#define GATE_IN     2608
#define GATE_IN_PAD 2624        // 41 * 64
#define STAT_W      576         // 560 data + 16 zero pad
#define GATE_HID    1024
#define NH          16
#define HD          128
#define NP          5
#define OUT_DIM     80
#define MAX_NT      8192

// GEMM1: CTA 128x256, 8 warps (2M x 4N, warp 64x64), fp16 m16n8k16 + ldmatrix
#define KCH         64                         // halves per K chunk (128 B)
#define NCHUNK      (GATE_IN_PAD / KCH)        // 41
#define STRH        72                         // padded halves per row
#define G1_A_H      (128 * STRH)
#define G1_B_H      (256 * STRH)
#define G1_STAGE_B  ((G1_A_H + G1_B_H) * 2)    // 55296 B
#define GEMM1_SMEM  (3 * G1_STAGE_B)           // 165888 B

// GEMM2: CTA 64(M) x 80(N), 8 warps (4M x 2N, warp 16x40), K=1024
#define G2_NCH      (GATE_HID / KCH)           // 16
#define G2_A_H      (64 * STRH)
#define G2_B_H      (80 * STRH)
#define GEMM2_SMEM  (2 * (G2_A_H + G2_B_H) * 2)

// Static scratch (fp16 operands)
__device__ __half g_hid_h[(size_t)MAX_NT * HIDDEN];
__device__ __half g_stats[(size_t)MAX_NT * STAT_W];
__device__ __half g_w1p[(size_t)GATE_HID * GATE_IN_PAD];
__device__ __half g_w2p[(size_t)OUT_DIM * GATE_HID];
__device__ __half g_h[(size_t)MAX_NT * GATE_HID];
__device__ float  g_probs[(size_t)MAX_NT * OUT_DIM];

// ---------------------------------------------------------------------------
// helpers
// ---------------------------------------------------------------------------
__device__ __forceinline__ float wredsum(float v) {
#pragma unroll
    for (int o = 16; o; o >>= 1) v += __shfl_xor_sync(0xffffffffu, v, o);
    return v;
}
__device__ __forceinline__ void cp_async16(uint32_t dst, const void* src) {
    asm volatile("cp.async.cg.shared.global [%0], [%1], 16;" :: "r"(dst), "l"(src));
}
__device__ __forceinline__ uint32_t smem_u32(const void* p) {
    uint32_t a;
    asm("{ .reg .u64 t; cvta.to.shared.u64 t, %1; cvt.u32.u64 %0, t; }" : "=r"(a) : "l"(p));
    return a;
}
__device__ __forceinline__ float gelu(float x) {
    return 0.5f * x * (1.0f + erff(x * 0.70710678118654752f));
}
__device__ __forceinline__ void ldmatrix_x4(uint32_t r[4], uint32_t addr) {
    asm volatile("ldmatrix.sync.aligned.m8n8.x4.shared.b16 {%0,%1,%2,%3}, [%4];"
                 : "=r"(r[0]), "=r"(r[1]), "=r"(r[2]), "=r"(r[3]) : "r"(addr));
}
// m16n8k16 f16, fp32 accum. c0=(g,2t) c1=(g,2t+1) c2=(g+8,2t) c3=(g+8,2t+1)
__device__ __forceinline__ void mma_f16_16x8x16(float c[4],
                                                uint32_t a0, uint32_t a1,
                                                uint32_t a2, uint32_t a3,
                                                uint32_t b0, uint32_t b1) {
    asm("mma.sync.aligned.m16n8k16.row.col.f32.f16.f16.f32 "
        "{%0,%1,%2,%3}, {%4,%5,%6,%7}, {%8,%9}, {%0,%1,%2,%3};"
        : "+f"(c[0]), "+f"(c[1]), "+f"(c[2]), "+f"(c[3])
        : "r"(a0), "r"(a1), "r"(a2), "r"(a3), "r"(b0), "r"(b1));
}

// ---------------------------------------------------------------------------
// Kernel A: path stats -> g_stats (fp16) + hidden -> g_hid_h (fp16).
// ---------------------------------------------------------------------------
__global__ void __launch_bounds__(512) stats_kernel(
    const float* __restrict__ hidden,
    const float* __restrict__ p0, const float* __restrict__ p1,
    const float* __restrict__ p2, const float* __restrict__ p3,
    const float* __restrict__ p4)
{
    const int t   = blockIdx.x;
    const int tid = threadIdx.x;
    __half* gate = g_stats + (size_t)t * STAT_W;

    {
        const float4 hv = (reinterpret_cast<const float4*>(hidden) + (size_t)t * (HIDDEN / 4))[tid];
        __half2 h0 = __floats2half2_rn(hv.x, hv.y);
        __half2 h1 = __floats2half2_rn(hv.z, hv.w);
        uint2 u;
        u.x = *reinterpret_cast<uint32_t*>(&h0);
        u.y = *reinterpret_cast<uint32_t*>(&h1);
        reinterpret_cast<uint2*>(g_hid_h + (size_t)t * HIDDEN)[tid] = u;
    }
    if (tid < 4) {
        uint2 z = {0u, 0u};
        reinterpret_cast<uint2*>(gate + 560)[tid] = z;
    }

    const int w = tid >> 5, lane = tid & 31;
    const float* pp[NP] = {p0, p1, p2, p3, p4};
    const size_t base = (size_t)t * (NH * HD) + (size_t)w * HD + lane * 4;

    float4 v[NP];
#pragma unroll
    for (int p = 0; p < NP; p++) v[p] = *reinterpret_cast<const float4*>(pp[p] + base);

    float vals[25];
#pragma unroll
    for (int p = 0; p < NP; p++) {
        vals[p]      = v[p].x + v[p].y + v[p].z + v[p].w;
        vals[5 + p]  = v[p].x * v[p].x + v[p].y * v[p].y + v[p].z * v[p].z + v[p].w * v[p].w;
        vals[10 + p] = fabsf(v[p].x) + fabsf(v[p].y) + fabsf(v[p].z) + fabsf(v[p].w);
    }
    {
        int k = 15;
#pragma unroll
        for (int p = 0; p < NP; p++)
#pragma unroll
            for (int q = p + 1; q < NP; q++)
                vals[k++] = v[p].x * v[q].x + v[p].y * v[q].y + v[p].z * v[q].z + v[p].w * v[q].w;
    }
#pragma unroll
    for (int i = 0; i < 25; i++) vals[i] = wredsum(vals[i]);

    if (lane == 0) {
        const float inv = 1.0f / 128.0f;
        float sq[NP];
#pragma unroll
        for (int p = 0; p < NP; p++) {
            float mean = vals[p] * inv;
            sq[p] = vals[5 + p];
            float l2 = sqrtf(sq[p]);
            float var = sq[p] * inv - mean * mean;
            float am  = vals[10 + p] * inv;
            __half* s = gate + w * (NP * 4) + p * 4;
            s[0] = __float2half_rn(mean); s[1] = __float2half_rn(var);
            s[2] = __float2half_rn(am);   s[3] = __float2half_rn(l2);
            gate[320 + w * NP + p] = __float2half_rn(l2);
        }
        int kk = 0;
#pragma unroll
        for (int p = 0; p < NP; p++)
#pragma unroll
            for (int q = p + 1; q < NP; q++) {
                float d2 = sq[p] + sq[q] - 2.0f * vals[15 + kk];
                gate[400 + w * 10 + kk] = __float2half_rn(sqrtf(fmaxf(d2, 0.0f)));
                kk++;
            }
    }
}

// ---------------------------------------------------------------------------
// Weight repacks -> fp16 (W1 zero-padded in K).
// ---------------------------------------------------------------------------
__global__ void pack_w1_kernel(const float* __restrict__ W1)
{
    const int idx = blockIdx.x * 256 + threadIdx.x;
    const int total = GATE_HID * (GATE_IN_PAD / 4);
    if (idx >= total) return;
    const int row = idx / (GATE_IN_PAD / 4);
    const int c4  = idx % (GATE_IN_PAD / 4);
    float4 v = {0.f, 0.f, 0.f, 0.f};
    if (c4 < GATE_IN / 4)
        v = reinterpret_cast<const float4*>(W1 + (size_t)row * GATE_IN)[c4];
    __half2 h0 = __floats2half2_rn(v.x, v.y);
    __half2 h1 = __floats2half2_rn(v.z, v.w);
    uint2 u;
    u.x = *reinterpret_cast<uint32_t*>(&h0);
    u.y = *reinterpret_cast<uint32_t*>(&h1);
    reinterpret_cast<uint2*>(g_w1p + (size_t)row * GATE_IN_PAD)[c4] = u;
}

__global__ void pack_w2_kernel(const float* __restrict__ W2)
{
    const int idx = blockIdx.x * 256 + threadIdx.x;
    const int total = OUT_DIM * (GATE_HID / 4);
    if (idx >= total) return;
    float4 v = reinterpret_cast<const float4*>(W2)[idx];
    __half2 h0 = __floats2half2_rn(v.x, v.y);
    __half2 h1 = __floats2half2_rn(v.z, v.w);
    uint2 u;
    u.x = *reinterpret_cast<uint32_t*>(&h0);
    u.y = *reinterpret_cast<uint32_t*>(&h1);
    reinterpret_cast<uint2*>(g_w2p)[idx] = u;
}

// ---------------------------------------------------------------------------
// Kernel B: GEMM1 fp16 mma + ldmatrix. h = fp16(GELU(gate @ W1p^T + b1))
// ---------------------------------------------------------------------------
__device__ __forceinline__ void g1_load(uint32_t stage_s,
                                        const __half* __restrict__ hid,
                                        const __half* __restrict__ st,
                                        const __half* __restrict__ Bm,
                                        int k0, int tid)
{
    const uint32_t a_s = stage_s;
    const uint32_t b_s = stage_s + G1_A_H * 2;
    const __half* asrc;
    int astride, ak;
    if (k0 < HIDDEN) { asrc = hid; astride = HIDDEN; ak = k0; }
    else             { asrc = st;  astride = STAT_W; ak = k0 - HIDDEN; }
#pragma unroll
    for (int j = 0; j < 4; j++) {
        const int idx = tid + j * 256;
        const int m  = idx >> 3;
        const int ks = (idx & 7) << 3;
        cp_async16(a_s + (uint32_t)(m * STRH + ks) * 2,
                   asrc + (size_t)m * astride + ak + ks);
    }
#pragma unroll
    for (int j = 0; j < 8; j++) {
        const int idx = tid + j * 256;
        const int m  = idx >> 3;
        const int ks = (idx & 7) << 3;
        cp_async16(b_s + (uint32_t)(m * STRH + ks) * 2,
                   Bm + (size_t)m * GATE_IN_PAD + k0 + ks);
    }
}

__global__ void __launch_bounds__(256, 1) gemm1_mma_kernel(const float* __restrict__ b1)
{
    extern __shared__ __half smem[];
    const uint32_t s0 = smem_u32(smem);

    const int tid  = threadIdx.x;
    const int wid  = tid >> 5, lane = tid & 31;
    const int wm   = (wid & 1) * 64;
    const int wn   = (wid >> 1) * 64;
    const int g    = lane >> 2;
    const int t2   = (lane & 3) * 2;
    const int quad = lane >> 3;

    // ldmatrix lane offsets (halves):
    //  A .x4 -> matrices (rows0-7,k-lo),(rows8-15,k-lo),(rows0-7,k-hi),(rows8-15,k-hi)
    const uint32_t a_loff = (uint32_t)(((quad & 1) * 8 + (lane & 7)) * STRH + (quad >> 1) * 8);
    //  B .x4 -> matrices (nj,k-lo),(nj,k-hi),(nj+1,k-lo),(nj+1,k-hi)
    const uint32_t b_loff = (uint32_t)(((quad >> 1) * 8 + (lane & 7)) * STRH + (quad & 1) * 8);

    const __half* hid = g_hid_h + (size_t)blockIdx.y * 128 * HIDDEN;
    const __half* st  = g_stats + (size_t)blockIdx.y * 128 * STAT_W;
    const __half* Bm  = g_w1p   + (size_t)blockIdx.x * 256 * GATE_IN_PAD;

    float acc[4][8][4];
#pragma unroll
    for (int i = 0; i < 4; i++)
#pragma unroll
        for (int j = 0; j < 8; j++)
#pragma unroll
            for (int r = 0; r < 4; r++) acc[i][j][r] = 0.0f;

    g1_load(s0, hid, st, Bm, 0, tid);
    asm volatile("cp.async.commit_group;" ::: "memory");
    g1_load(s0 + G1_STAGE_B, hid, st, Bm, KCH, tid);
    asm volatile("cp.async.commit_group;" ::: "memory");

    int stage_rd = 0;
    for (int i = 0; i < NCHUNK; i++) {
        if (i + 2 < NCHUNK) {
            const int ws = (i + 2) % 3;
            g1_load(s0 + (uint32_t)ws * G1_STAGE_B, hid, st, Bm, (i + 2) * KCH, tid);
        }
        asm volatile("cp.async.commit_group;" ::: "memory");
        asm volatile("cp.async.wait_group 2;" ::: "memory");
        __syncthreads();

        const uint32_t as_u = s0 + (uint32_t)stage_rd * G1_STAGE_B;
        const uint32_t bs_u = as_u + G1_A_H * 2;

#pragma unroll
        for (int kk = 0; kk < KCH; kk += 16) {
            uint32_t a[4][4];
#pragma unroll
            for (int mi = 0; mi < 4; mi++)
                ldmatrix_x4(a[mi],
                            as_u + ((uint32_t)((wm + mi * 16) * STRH + kk) + a_loff) * 2);
            uint32_t b[4][4];   // b[njp] = {b0(nj0), b1(nj0), b0(nj1), b1(nj1)}
#pragma unroll
            for (int njp = 0; njp < 4; njp++)
                ldmatrix_x4(b[njp],
                            bs_u + ((uint32_t)((wn + njp * 16) * STRH + kk) + b_loff) * 2);
#pragma unroll
            for (int mi = 0; mi < 4; mi++)
#pragma unroll
                for (int njp = 0; njp < 4; njp++) {
                    mma_f16_16x8x16(acc[mi][njp * 2],     a[mi][0], a[mi][1], a[mi][2], a[mi][3],
                                    b[njp][0], b[njp][1]);
                    mma_f16_16x8x16(acc[mi][njp * 2 + 1], a[mi][0], a[mi][1], a[mi][2], a[mi][3],
                                    b[njp][2], b[njp][3]);
                }
        }
        __syncthreads();
        stage_rd = stage_rd + 1 == 3 ? 0 : stage_rd + 1;
    }

    // epilogue: bias + exact GELU -> fp16 g_h
    const size_t row_base = (size_t)blockIdx.y * 128 + wm + g;
    const int    col_base = blockIdx.x * 256 + wn + t2;
#pragma unroll
    for (int nj = 0; nj < 8; nj++) {
        const int gc = col_base + nj * 8;
        const float2 bb = *reinterpret_cast<const float2*>(b1 + gc);
#pragma unroll
        for (int mi = 0; mi < 4; mi++) {
            const size_t r0 = row_base + mi * 16;
            __half2 o0 = __floats2half2_rn(gelu(acc[mi][nj][0] + bb.x),
                                           gelu(acc[mi][nj][1] + bb.y));
            __half2 o1 = __floats2half2_rn(gelu(acc[mi][nj][2] + bb.x),
                                           gelu(acc[mi][nj][3] + bb.y));
            *reinterpret_cast<__half2*>(g_h + r0 * GATE_HID + gc)       = o0;
            *reinterpret_cast<__half2*>(g_h + (r0 + 8) * GATE_HID + gc) = o1;
        }
    }
}

// ---------------------------------------------------------------------------
// Kernel C: GEMM2 fp16 mma + fused bias/softmax/clip/renorm.
// ---------------------------------------------------------------------------
__global__ void __launch_bounds__(256) gemm2_mma_kernel(
    const float* __restrict__ b2, const float* __restrict__ log_temp)
{
    extern __shared__ __half smem[];
    const uint32_t s0 = smem_u32(smem);

    const int tid  = threadIdx.x;
    const int wid  = tid >> 5, lane = tid & 31;
    const int mw   = wid >> 1;
    const int nw   = wid & 1;
    const int g    = lane >> 2;
    const int t2   = (lane & 3) * 2;

    const int tbase = blockIdx.x * 64;
    const __half* A = g_h + (size_t)tbase * GATE_HID;

    float acc[5][4];
#pragma unroll
    for (int j = 0; j < 5; j++)
#pragma unroll
        for (int r = 0; r < 4; r++) acc[j][r] = 0.0f;

    const uint32_t aoff[2] = {0u, (uint32_t)G2_A_H * 2};
    const uint32_t boff[2] = {(uint32_t)(2 * G2_A_H) * 2,
                              (uint32_t)(2 * G2_A_H + G2_B_H) * 2};

    {
#pragma unroll
        for (int j = 0; j < 2; j++) {
            const int idx = tid + j * 256;
            const int m = idx >> 3, ks = (idx & 7) << 3;
            cp_async16(s0 + aoff[0] + (uint32_t)(m * STRH + ks) * 2,
                       A + (size_t)m * GATE_HID + ks);
        }
#pragma unroll
        for (int j = 0; j < 3; j++) {
            const int idx = tid + j * 256;
            if (idx < 640) {
                const int m = idx >> 3, ks = (idx & 7) << 3;
                cp_async16(s0 + boff[0] + (uint32_t)(m * STRH + ks) * 2,
                           g_w2p + (size_t)m * GATE_HID + ks);
            }
        }
        asm volatile("cp.async.commit_group;" ::: "memory");
    }

    for (int i = 0; i < G2_NCH; i++) {
        const int s = i & 1;
        if (i + 1 < G2_NCH) {
            const int ns = (i + 1) & 1;
            const int k0 = (i + 1) * KCH;
#pragma unroll
            for (int j = 0; j < 2; j++) {
                const int idx = tid + j * 256;
                const int m = idx >> 3, ks = (idx & 7) << 3;
                cp_async16(s0 + aoff[ns] + (uint32_t)(m * STRH + ks) * 2,
                           A + (size_t)m * GATE_HID + k0 + ks);
            }
#pragma unroll
            for (int j = 0; j < 3; j++) {
                const int idx = tid + j * 256;
                if (idx < 640) {
                    const int m = idx >> 3, ks = (idx & 7) << 3;
                    cp_async16(s0 + boff[ns] + (uint32_t)(m * STRH + ks) * 2,
                               g_w2p + (size_t)m * GATE_HID + k0 + ks);
                }
            }
        }
        asm volatile("cp.async.commit_group;" ::: "memory");
        if (i + 1 < G2_NCH) asm volatile("cp.async.wait_group 1;" ::: "memory");
        else                asm volatile("cp.async.wait_group 0;" ::: "memory");
        __syncthreads();

        const __half* as = smem + (s ? G2_A_H : 0);
        const __half* bs = smem + 2 * G2_A_H + (s ? G2_B_H : 0);

#pragma unroll
        for (int kk = 0; kk < KCH; kk += 16) {
            const __half* r0 = as + (mw * 16 + g) * STRH + kk + t2;
            const __half* r1 = as + (mw * 16 + g + 8) * STRH + kk + t2;
            uint32_t a0 = *reinterpret_cast<const uint32_t*>(r0);
            uint32_t a1 = *reinterpret_cast<const uint32_t*>(r1);
            uint32_t a2 = *reinterpret_cast<const uint32_t*>(r0 + 8);
            uint32_t a3 = *reinterpret_cast<const uint32_t*>(r1 + 8);
#pragma unroll
            for (int nj = 0; nj < 5; nj++) {
                const __half* br = bs + (nw * 40 + nj * 8 + g) * STRH + kk + t2;
                mma_f16_16x8x16(acc[nj], a0, a1, a2, a3,
                                *reinterpret_cast<const uint32_t*>(br),
                                *reinterpret_cast<const uint32_t*>(br + 8));
            }
        }
        __syncthreads();
    }

    float* lg = reinterpret_cast<float*>(smem);
    {
        const int r0 = mw * 16 + g;
        const int c0 = nw * 40 + t2;
#pragma unroll
        for (int nj = 0; nj < 5; nj++) {
            const int c = c0 + nj * 8;
            lg[r0 * OUT_DIM + c]            = acc[nj][0];
            lg[r0 * OUT_DIM + c + 1]        = acc[nj][1];
            lg[(r0 + 8) * OUT_DIM + c]      = acc[nj][2];
            lg[(r0 + 8) * OUT_DIM + c + 1]  = acc[nj][3];
        }
    }
    __syncthreads();

#pragma unroll
    for (int it = 0; it < 4; it++) {
        const int idx = tid + it * 256;
        const int tt = idx >> 4, h = idx & 15;
        const float invt = expf(-log_temp[h]);
        float l[NP], mx = -1e30f;
#pragma unroll
        for (int p = 0; p < NP; p++) {
            l[p] = (lg[tt * OUT_DIM + h * NP + p] + __ldg(b2 + h * NP + p)) * invt;
            mx = fmaxf(mx, l[p]);
        }
        float e[NP], se = 0.f;
#pragma unroll
        for (int p = 0; p < NP; p++) { e[p] = expf(l[p] - mx); se += e[p]; }
        const float ise = 1.0f / se;
        float pr[NP], s2s = 0.f;
#pragma unroll
        for (int p = 0; p < NP; p++) { pr[p] = fmaxf(e[p] * ise, 0.02f); s2s += pr[p]; }
        const float is2 = 1.0f / s2s;
        float* dst = g_probs + (size_t)(tbase + tt) * OUT_DIM + h * NP;
#pragma unroll
        for (int p = 0; p < NP; p++) dst[p] = pr[p] * is2;
    }
}

// ---------------------------------------------------------------------------
// Kernel D: weighted path combine.
// ---------------------------------------------------------------------------
__global__ void output_kernel(
    const float* __restrict__ p0, const float* __restrict__ p1,
    const float* __restrict__ p2, const float* __restrict__ p3,
    const float* __restrict__ p4, float* __restrict__ out, int n4)
{
    const int v = blockIdx.x * blockDim.x + threadIdx.x;
    if (v >= n4) return;
    const int t = v >> 9;
    const int h = (v >> 5) & 15;
    const float* pb = g_probs + (size_t)t * OUT_DIM + h * NP;
    const float w0 = pb[0], w1 = pb[1], w2 = pb[2], w3 = pb[3], w4 = pb[4];
    const float4 a0 = reinterpret_cast<const float4*>(p0)[v];
    const float4 a1 = reinterpret_cast<const float4*>(p1)[v];
    const float4 a2 = reinterpret_cast<const float4*>(p2)[v];
    const float4 a3 = reinterpret_cast<const float4*>(p3)[v];
    const float4 a4 = reinterpret_cast<const float4*>(p4)[v];
    float4 o;
    o.x = a0.x * w0 + a1.x * w1 + a2.x * w2 + a3.x * w3 + a4.x * w4;
    o.y = a0.y * w0 + a1.y * w1 + a2.y * w2 + a3.y * w3 + a4.y * w4;
    o.z = a0.z * w0 + a1.z * w1 + a2.z * w2 + a3.z * w3 + a4.z * w4;
    o.w = a0.w * w0 + a1.w * w1 + a2.w * w2 + a3.w * w3 + a4.w * w4;
    reinterpret_cast<float4*>(out)[v] = o;
}

__global__ void zero_tail_kernel(float* out, int start, int total)
{
    const int i = start + blockIdx.x * blockDim.x + threadIdx.x;
    if (i < total) out[i] = 0.0f;
}

// ---------------------------------------------------------------------------
extern "C" void kernel_launch(void* const* d_in, const int* in_sizes, int n_in,
                              void* d_out, int out_size)
{
    const float* hidden = (const float*)d_in[0];
    const float* p0 = (const float*)d_in[1];
    const float* p1 = (const float*)d_in[2];
    const float* p2 = (const float*)d_in[3];
    const float* p3 = (const float*)d_in[4];
    const float* p4 = (const float*)d_in[5];
    const float* W1 = (const float*)d_in[6];
    const float* b1 = (const float*)d_in[7];
    const float* W2 = (const float*)d_in[8];
    const float* b2 = (const float*)d_in[9];
    const float* lt = (const float*)d_in[10];

    const int NT = in_sizes[0] / HIDDEN;   // 8192

    static int smem_set = 0;
    if (!smem_set) {
        cudaFuncSetAttribute(gemm1_mma_kernel,
                             cudaFuncAttributeMaxDynamicSharedMemorySize, GEMM1_SMEM);
        cudaFuncSetAttribute(gemm2_mma_kernel,
                             cudaFuncAttributeMaxDynamicSharedMemorySize, GEMM2_SMEM);
        smem_set = 1;
    }

    {
        const int t1 = GATE_HID * (GATE_IN_PAD / 4);
        pack_w1_kernel<<<(t1 + 255) / 256, 256>>>(W1);
        const int t2 = OUT_DIM * (GATE_HID / 4);
        pack_w2_kernel<<<(t2 + 255) / 256, 256>>>(W2);
    }
    stats_kernel<<<NT, 512>>>(hidden, p0, p1, p2, p3, p4);

    dim3 g1(GATE_HID / 256, NT / 128);   // (4, 64)
    gemm1_mma_kernel<<<g1, 256, GEMM1_SMEM>>>(b1);

    gemm2_mma_kernel<<<NT / 64, 256, GEMM2_SMEM>>>(b2, lt);

    const int n4 = NT * (NH * HD) / 4;
    output_kernel<<<(n4 + 255) / 256, 256>>>(p0, p1, p2, p3, p4, (float*)d_out, n4);

    const int nout = NT * NH * HD;
    if (out_size > nout) {
        const int extra = out_size - nout;
        zero_tail_kernel<<<(extra + 255) / 256, 256>>>((float*)d_out, nout, out_size);
    }
}